// round 3
// baseline (speedup 1.0000x reference)
#include <cuda_runtime.h>
#include <math.h>

#define NL 3
#define DD 512
#define NV 100
#define NB 128
#define NS 512
#define NSE 512
#define MALL (NB*NS)
#define D3 (3*DD)

__device__ float g_xbuf[(size_t)MALL * DD];
__device__ float g_xp[(size_t)MALL * D3];
__device__ float g_ctx[(size_t)MALL * DD];
__device__ float g_hA[NB * DD];
__device__ float g_hB[NB * DD];
__device__ float g_mask[MALL];
__device__ unsigned g_cnt = 0;
__device__ volatile unsigned g_gen = 0;

// ---- f32x2 helpers ----
__device__ __forceinline__ unsigned long long fma2(unsigned long long a, unsigned long long b, unsigned long long c) {
    unsigned long long d;
    asm("fma.rn.f32x2 %0, %1, %2, %3;" : "=l"(d) : "l"(a), "l"(b), "l"(c));
    return d;
}
__device__ __forceinline__ unsigned long long pack2(float x, float y) {
    unsigned long long d;
    asm("mov.b64 %0, {%1, %2};" : "=l"(d) : "f"(x), "f"(y));
    return d;
}
__device__ __forceinline__ float2 unpack2(unsigned long long v) {
    float2 r;
    asm("mov.b64 {%0, %1}, %2;" : "=f"(r.x), "=f"(r.y) : "l"(v));
    return r;
}

__global__ void embed_kernel(const int* __restrict__ seqs,
                             const float* __restrict__ emb,
                             float* __restrict__ xbuf) {
    size_t i = (size_t)blockIdx.x * blockDim.x + threadIdx.x;
    size_t row = i >> 7;
    int c = (int)(i & 127);
    int tok = seqs[row];
    ((float4*)xbuf)[i] = ((const float4*)(emb + (size_t)tok * DD))[c];
}

__global__ void copy4_kernel(float* __restrict__ dst, const float* __restrict__ src, int n4) {
    int i = blockIdx.x * blockDim.x + threadIdx.x;
    if (i < n4) ((float4*)dst)[i] = ((const float4*)src)[i];
}

__global__ void mask_kernel(const float* __restrict__ xbuf, float* __restrict__ maskp) {
    int m = blockIdx.x * blockDim.x + threadIdx.x;
    if (m < MALL) maskp[m] = (xbuf[(size_t)m * DD] != 0.0f) ? 1.0f : 0.0f;
}

__global__ void softmax_kernel(float* __restrict__ P) {
    __shared__ float red[256];
    float* p = P + (size_t)blockIdx.x * NSE;
    int tid = threadIdx.x;
    float v0 = p[tid], v1 = p[tid + 256];
    red[tid] = fmaxf(v0, v1); __syncthreads();
    #pragma unroll
    for (int s = 128; s > 0; s >>= 1) { if (tid < s) red[tid] = fmaxf(red[tid], red[tid + s]); __syncthreads(); }
    float mx = red[0]; __syncthreads();
    float e0 = expf(v0 - mx), e1 = expf(v1 - mx);
    red[tid] = e0 + e1; __syncthreads();
    #pragma unroll
    for (int s = 128; s > 0; s >>= 1) { if (tid < s) red[tid] += red[tid + s]; __syncthreads(); }
    float inv = 1.0f / red[0];
    p[tid] = e0 * inv; p[tid + 256] = e1 * inv;
}

// C = scale*(A @ W^T) + bias; optional concat A=[A0|A1] along K (both row-stride K0).
// epi: 0 none, 1 tanh(v)*mask[row], 2 v*mask[row]
__global__ void __launch_bounds__(256) gemm_nt(
    const float* __restrict__ A0, const float* __restrict__ A1, int K0, int K,
    const float* __restrict__ Wm, const float* __restrict__ bias,
    float* __restrict__ C, int N,
    size_t sA, size_t sW, size_t sC,
    float scale, const float* __restrict__ mask, int epi)
{
    __shared__ __align__(16) float As[8][128];
    __shared__ __align__(16) float Bs[8][128];
    int bz = blockIdx.z;
    const float* Ab = A0 + (size_t)bz * sA;
    const float* Wb = Wm + (size_t)bz * sW;
    float* Cb       = C  + (size_t)bz * sC;
    int mBase = blockIdx.y * 128, nBase = blockIdx.x * 128;
    int tid = threadIdx.x, tx = tid & 15, ty = tid >> 4;
    unsigned long long acc2[8][4];
    #pragma unroll
    for (int i = 0; i < 8; i++)
        #pragma unroll
        for (int j = 0; j < 4; j++) acc2[i][j] = 0ULL;
    int lr = tid >> 1, lk = (tid & 1) * 4;

    for (int kk = 0; kk < K; kk += 8) {
        const float* Ap; int kc;
        if (kk < K0) { Ap = Ab; kc = kk; } else { Ap = A1; kc = kk - K0; }
        float4 av = *(const float4*)(Ap + (size_t)(mBase + lr) * K0 + kc + lk);
        float4 wv = make_float4(0.f,0.f,0.f,0.f);
        int wrow = nBase + lr;
        if (wrow < N) wv = *(const float4*)(Wb + (size_t)wrow * K + kk + lk);
        __syncthreads();
        As[lk+0][lr]=av.x; As[lk+1][lr]=av.y; As[lk+2][lr]=av.z; As[lk+3][lr]=av.w;
        Bs[lk+0][lr]=wv.x; Bs[lk+1][lr]=wv.y; Bs[lk+2][lr]=wv.z; Bs[lk+3][lr]=wv.w;
        __syncthreads();
        #pragma unroll
        for (int k = 0; k < 8; k++) {
            float4 a0 = *(float4*)&As[k][ty*8], a1 = *(float4*)&As[k][ty*8+4];
            ulonglong2 bA = *(ulonglong2*)&Bs[k][tx*8];
            ulonglong2 bB = *(ulonglong2*)&Bs[k][tx*8+4];
            float ar[8] = {a0.x,a0.y,a0.z,a0.w,a1.x,a1.y,a1.z,a1.w};
            #pragma unroll
            for (int i = 0; i < 8; i++) {
                unsigned long long ad = pack2(ar[i], ar[i]);
                acc2[i][0] = fma2(ad, bA.x, acc2[i][0]);
                acc2[i][1] = fma2(ad, bA.y, acc2[i][1]);
                acc2[i][2] = fma2(ad, bB.x, acc2[i][2]);
                acc2[i][3] = fma2(ad, bB.y, acc2[i][3]);
            }
        }
    }
    #pragma unroll
    for (int i = 0; i < 8; i++) {
        int row = mBase + ty*8 + i;
        float mk = 1.0f;
        if (epi != 0) mk = mask[row];
        #pragma unroll
        for (int jp = 0; jp < 4; jp++) {
            float2 cp = unpack2(acc2[i][jp]);
            float vv[2] = {cp.x, cp.y};
            #pragma unroll
            for (int q = 0; q < 2; q++) {
                int col = nBase + tx*8 + jp*2 + q;
                if (col < N) {
                    float v = vv[q] * scale;
                    if (bias) v += bias[col];
                    if (epi == 1) v = tanhf(v) * mk;
                    else if (epi == 2) v = v * mk;
                    Cb[(size_t)row * N + col] = v;
                }
            }
        }
    }
}

// batched C = A @ B
__global__ void __launch_bounds__(256) gemm_nn(
    const float* __restrict__ A, const float* __restrict__ Bm,
    float* __restrict__ C, int K, int N,
    size_t sA, size_t sB, size_t sC)
{
    __shared__ __align__(16) float As[8][128];
    __shared__ __align__(16) float Bs[8][128];
    int bz = blockIdx.z;
    const float* Ab = A  + (size_t)bz * sA;
    const float* Bb = Bm + (size_t)bz * sB;
    float* Cb       = C  + (size_t)bz * sC;
    int mBase = blockIdx.y * 128, nBase = blockIdx.x * 128;
    int tid = threadIdx.x, tx = tid & 15, ty = tid >> 4;
    unsigned long long acc2[8][4];
    #pragma unroll
    for (int i = 0; i < 8; i++)
        #pragma unroll
        for (int j = 0; j < 4; j++) acc2[i][j] = 0ULL;
    int alr = tid >> 1, alk = (tid & 1) * 4;
    int bkr = tid >> 5, bnc = (tid & 31) * 4;

    for (int kk = 0; kk < K; kk += 8) {
        float4 av = *(const float4*)(Ab + (size_t)(mBase + alr) * K + kk + alk);
        float4 bv = *(const float4*)(Bb + (size_t)(kk + bkr) * N + nBase + bnc);
        __syncthreads();
        As[alk+0][alr]=av.x; As[alk+1][alr]=av.y; As[alk+2][alr]=av.z; As[alk+3][alr]=av.w;
        *(float4*)&Bs[bkr][bnc] = bv;
        __syncthreads();
        #pragma unroll
        for (int k = 0; k < 8; k++) {
            float4 a0 = *(float4*)&As[k][ty*8], a1 = *(float4*)&As[k][ty*8+4];
            ulonglong2 bA = *(ulonglong2*)&Bs[k][tx*8];
            ulonglong2 bB = *(ulonglong2*)&Bs[k][tx*8+4];
            float ar[8] = {a0.x,a0.y,a0.z,a0.w,a1.x,a1.y,a1.z,a1.w};
            #pragma unroll
            for (int i = 0; i < 8; i++) {
                unsigned long long ad = pack2(ar[i], ar[i]);
                acc2[i][0] = fma2(ad, bA.x, acc2[i][0]);
                acc2[i][1] = fma2(ad, bA.y, acc2[i][1]);
                acc2[i][2] = fma2(ad, bB.x, acc2[i][2]);
                acc2[i][3] = fma2(ad, bB.y, acc2[i][3]);
            }
        }
    }
    #pragma unroll
    for (int i = 0; i < 8; i++) {
        int row = mBase + ty*8 + i;
        #pragma unroll
        for (int jp = 0; jp < 4; jp++) {
            float2 cp = unpack2(acc2[i][jp]);
            Cb[(size_t)row * N + nBase + tx*8 + jp*2 + 0] = cp.x;
            Cb[(size_t)row * N + nBase + tx*8 + jp*2 + 1] = cp.y;
        }
    }
}

// ---- software grid barrier (128 co-resident blocks) ----
__device__ __forceinline__ void grid_bar() {
    __syncthreads();
    if (threadIdx.x == 0) {
        __threadfence();
        unsigned gen = g_gen;
        unsigned old = atomicAdd(&g_cnt, 1);
        if (old == 127u) {
            atomicExch(&g_cnt, 0u);
            __threadfence();
            g_gen = gen + 1u;
        } else {
            while (g_gen == gen) { }
        }
        __threadfence();
    }
    __syncthreads();
}

// persistent per-layer GRU: 128 blocks (16 j-tiles x 8 m-tiles), 128 threads.
// W_hh slice resident in smem for all 512 steps.
#define WS_LD 516
#define GRU_SMEM ((3*32*WS_LD + 16*DD) * 4)
__global__ void __launch_bounds__(128, 1) gru_layer(
    float* __restrict__ hA, float* __restrict__ hB,
    const float* __restrict__ W, const float* __restrict__ bhh,
    const float* __restrict__ xp, float* __restrict__ y)
{
    extern __shared__ float sm[];
    float* ws = sm;                    // [3][32][WS_LD]
    float* hs = sm + 3 * 32 * WS_LD;   // [16][512]
    int tid = threadIdx.x, tx = tid & 31, ty = tid >> 5;
    int jb = blockIdx.x & 15, mb = blockIdx.x >> 4;
    int jBase = jb * 32, mBase = mb * 16;

    // stage W_hh slice (96 rows x 512) into smem once
    #pragma unroll 1
    for (int r = 0; r < 96; r++) {
        int g = r >> 5, jr = r & 31;
        float4 v = *(const float4*)(W + (size_t)(g * DD + jBase + jr) * DD + tid * 4);
        *(float4*)&ws[(g * 32 + jr) * WS_LD + tid * 4] = v;
    }
    int j = jBase + tx;
    float brv = bhh[j], bzv = bhh[DD + j], bnv = bhh[2 * DD + j];
    const float* wr0 = &ws[(0 * 32 + tx) * WS_LD];
    const float* wr1 = &ws[(1 * 32 + tx) * WS_LD];
    const float* wr2 = &ws[(2 * 32 + tx) * WS_LD];
    const float* hr  = &hs[(ty * 4) * DD];

    for (int t = 0; t < NS; t++) {
        const float* hin = (t & 1) ? hB : hA;
        float*       hout = (t & 1) ? hA : hB;
        #pragma unroll
        for (int it = 0; it < 16; it++)
            *(float4*)&hs[it * DD + tid * 4] =
                *(const float4*)(hin + (size_t)(mBase + it) * DD + tid * 4);
        __syncthreads();

        unsigned long long acc[3][4];
        #pragma unroll
        for (int g = 0; g < 3; g++)
            #pragma unroll
            for (int i = 0; i < 4; i++) acc[g][i] = 0ULL;

        #pragma unroll 4
        for (int k = 0; k < DD; k += 4) {
            ulonglong2 w0 = *(const ulonglong2*)(wr0 + k);
            ulonglong2 w1 = *(const ulonglong2*)(wr1 + k);
            ulonglong2 w2 = *(const ulonglong2*)(wr2 + k);
            #pragma unroll
            for (int i = 0; i < 4; i++) {
                ulonglong2 hv = *(const ulonglong2*)(hr + i * DD + k);
                acc[0][i] = fma2(hv.x, w0.x, acc[0][i]);
                acc[0][i] = fma2(hv.y, w0.y, acc[0][i]);
                acc[1][i] = fma2(hv.x, w1.x, acc[1][i]);
                acc[1][i] = fma2(hv.y, w1.y, acc[1][i]);
                acc[2][i] = fma2(hv.x, w2.x, acc[2][i]);
                acc[2][i] = fma2(hv.y, w2.y, acc[2][i]);
            }
        }
        #pragma unroll
        for (int i = 0; i < 4; i++) {
            int m = mBase + ty * 4 + i;
            float2 p0 = unpack2(acc[0][i]);
            float2 p1 = unpack2(acc[1][i]);
            float2 p2 = unpack2(acc[2][i]);
            float gr = p0.x + p0.y, gz = p1.x + p1.y, gn = p2.x + p2.y;
            size_t base = ((size_t)m * NS + t) * D3;
            float xr = xp[base + j], xz = xp[base + DD + j], xn = xp[base + 2 * DD + j];
            float r = 1.0f / (1.0f + expf(-(xr + gr + brv)));
            float z = 1.0f / (1.0f + expf(-(xz + gz + bzv)));
            float n = tanhf(xn + r * (gn + bnv));
            float hprev = hs[(ty * 4 + i) * DD + j];
            float h2 = (1.0f - z) * n + z * hprev;
            hout[(size_t)m * DD + j] = h2;
            y[((size_t)m * NS + t) * DD + j] = h2;
        }
        grid_bar();
    }
}

extern "C" void kernel_launch(void* const* d_in, const int* in_sizes, int n_in,
                              void* d_out, int out_size) {
    const int*   seqs  = (const int*)d_in[0];
    const float* enc   = (const float*)d_in[2];
    const float* h0    = (const float*)d_in[3];
    const float* emb   = (const float*)d_in[4];
    const float* w_ih  = (const float*)d_in[5];
    const float* w_hh  = (const float*)d_in[6];
    const float* b_ih  = (const float*)d_in[7];
    const float* b_hh  = (const float*)d_in[8];
    const float* attnw = (const float*)d_in[9];
    const float* attnb = (const float*)d_in[10];
    const float* outw  = (const float*)d_in[11];
    const float* outb  = (const float*)d_in[12];
    float* out = (float*)d_out;

    float *xbuf, *xp, *ctx, *hA, *hB, *mask;
    cudaGetSymbolAddress((void**)&xbuf, g_xbuf);
    cudaGetSymbolAddress((void**)&xp,   g_xp);
    cudaGetSymbolAddress((void**)&ctx,  g_ctx);
    cudaGetSymbolAddress((void**)&hA,   g_hA);
    cudaGetSymbolAddress((void**)&hB,   g_hB);
    cudaGetSymbolAddress((void**)&mask, g_mask);

    static int smem_set = 0;
    if (!smem_set) {
        cudaFuncSetAttribute(gru_layer, cudaFuncAttributeMaxDynamicSharedMemorySize, GRU_SMEM);
        smem_set = 1;
    }

    const size_t OUT_H    = (size_t)MALL * NV;
    const size_t OUT_ATTN = OUT_H + (size_t)NL * NB * DD;
    float* attnP = out + OUT_ATTN;

    embed_kernel<<<(MALL * (DD/4)) / 256, 256>>>(seqs, emb, xbuf);

    for (int l = 0; l < NL; l++) {
        gemm_nt<<<dim3(D3/128, MALL/128, 1), 256>>>(
            xbuf, nullptr, DD, DD,
            w_ih + (size_t)l * D3 * DD, b_ih + (size_t)l * D3,
            xp, D3, 0, 0, 0, 1.0f, nullptr, 0);
        copy4_kernel<<<64, 256>>>(hA, h0 + (size_t)l * NB * DD, NB * DD / 4);
        gru_layer<<<128, 128, GRU_SMEM>>>(
            hA, hB, w_hh + (size_t)l * D3 * DD, b_hh + (size_t)l * D3, xp, xbuf);
        copy4_kernel<<<64, 256>>>(out + OUT_H + (size_t)l * NB * DD, hA, NB * DD / 4);
    }

    mask_kernel<<<MALL / 256, 256>>>(xbuf, mask);

    gemm_nt<<<dim3(NSE/128, NS/128, NB), 256>>>(
        xbuf, nullptr, DD, DD, enc, nullptr,
        attnP, NSE,
        (size_t)NS * DD, (size_t)NSE * DD, (size_t)NS * NSE,
        0.044194173824159216f, nullptr, 0);
    softmax_kernel<<<MALL, 256>>>(attnP);

    gemm_nn<<<dim3(DD/128, NS/128, NB), 256>>>(
        attnP, enc, ctx, NSE, DD,
        (size_t)NS * NSE, (size_t)NSE * DD, (size_t)NS * DD);

    gemm_nt<<<dim3(DD/128, MALL/128, 1), 256>>>(
        xbuf, ctx, DD, 2 * DD, attnw, attnb,
        xp, DD, 0, 0, 0, 1.0f, mask, 1);

    gemm_nt<<<dim3(1, MALL/128, 1), 256>>>(
        xp, nullptr, DD, DD, outw, outb,
        out, NV, 0, 0, 0, 1.0f, mask, 2);
}

// round 4
// speedup vs baseline: 1.0098x; 1.0098x over previous
#include <cuda_runtime.h>
#include <math.h>

#define NL 3
#define DD 512
#define NV 100
#define NB 128
#define NS 512
#define NSE 512
#define MALL (NB*NS)
#define D3 (3*DD)

__device__ float g_xbuf[(size_t)MALL * DD];
__device__ float g_xp[(size_t)MALL * D3];
__device__ float g_ctx[(size_t)MALL * DD];
__device__ float g_hA[NB * DD];
__device__ float g_hB[NB * DD];
__device__ float g_mask[MALL];
__device__ unsigned g_cnt8[8];
__device__ volatile unsigned g_gen8[8];

// ---- f32x2 helpers ----
__device__ __forceinline__ unsigned long long fma2(unsigned long long a, unsigned long long b, unsigned long long c) {
    unsigned long long d;
    asm("fma.rn.f32x2 %0, %1, %2, %3;" : "=l"(d) : "l"(a), "l"(b), "l"(c));
    return d;
}
__device__ __forceinline__ unsigned long long pack2(float x, float y) {
    unsigned long long d;
    asm("mov.b64 %0, {%1, %2};" : "=l"(d) : "f"(x), "f"(y));
    return d;
}
__device__ __forceinline__ float2 unpack2(unsigned long long v) {
    float2 r;
    asm("mov.b64 {%0, %1}, %2;" : "=f"(r.x), "=f"(r.y) : "l"(v));
    return r;
}
__device__ __forceinline__ float tanh_fast(float x) {
    float y;
    asm("tanh.approx.f32 %0, %1;" : "=f"(y) : "f"(x));
    return y;
}
__device__ __forceinline__ float sigmoid_fast(float x) {
    return 1.0f / (1.0f + __expf(-x));
}

__global__ void embed_kernel(const int* __restrict__ seqs,
                             const float* __restrict__ emb,
                             float* __restrict__ xbuf) {
    size_t i = (size_t)blockIdx.x * blockDim.x + threadIdx.x;
    size_t row = i >> 7;
    int c = (int)(i & 127);
    int tok = seqs[row];
    ((float4*)xbuf)[i] = ((const float4*)(emb + (size_t)tok * DD))[c];
}

__global__ void copy4_kernel(float* __restrict__ dst, const float* __restrict__ src, int n4) {
    int i = blockIdx.x * blockDim.x + threadIdx.x;
    if (i < n4) ((float4*)dst)[i] = ((const float4*)src)[i];
}

__global__ void mask_kernel(const float* __restrict__ xbuf, float* __restrict__ maskp) {
    int m = blockIdx.x * blockDim.x + threadIdx.x;
    if (m < MALL) maskp[m] = (xbuf[(size_t)m * DD] != 0.0f) ? 1.0f : 0.0f;
}

__global__ void softmax_kernel(float* __restrict__ P) {
    __shared__ float red[256];
    float* p = P + (size_t)blockIdx.x * NSE;
    int tid = threadIdx.x;
    float v0 = p[tid], v1 = p[tid + 256];
    red[tid] = fmaxf(v0, v1); __syncthreads();
    #pragma unroll
    for (int s = 128; s > 0; s >>= 1) { if (tid < s) red[tid] = fmaxf(red[tid], red[tid + s]); __syncthreads(); }
    float mx = red[0]; __syncthreads();
    float e0 = __expf(v0 - mx), e1 = __expf(v1 - mx);
    red[tid] = e0 + e1; __syncthreads();
    #pragma unroll
    for (int s = 128; s > 0; s >>= 1) { if (tid < s) red[tid] += red[tid + s]; __syncthreads(); }
    float inv = 1.0f / red[0];
    p[tid] = e0 * inv; p[tid + 256] = e1 * inv;
}

// C = scale*(A @ W^T) + bias; optional concat A=[A0|A1] along K (both row-stride K0).
// epi: 0 none, 1 tanh(v)*mask[row], 2 v*mask[row]
__global__ void __launch_bounds__(256) gemm_nt(
    const float* __restrict__ A0, const float* __restrict__ A1, int K0, int K,
    const float* __restrict__ Wm, const float* __restrict__ bias,
    float* __restrict__ C, int N,
    size_t sA, size_t sW, size_t sC,
    float scale, const float* __restrict__ mask, int epi)
{
    __shared__ __align__(16) float As[8][128];
    __shared__ __align__(16) float Bs[8][128];
    int bz = blockIdx.z;
    const float* Ab = A0 + (size_t)bz * sA;
    const float* Wb = Wm + (size_t)bz * sW;
    float* Cb       = C  + (size_t)bz * sC;
    int mBase = blockIdx.y * 128, nBase = blockIdx.x * 128;
    int tid = threadIdx.x, tx = tid & 15, ty = tid >> 4;
    unsigned long long acc2[8][4];
    #pragma unroll
    for (int i = 0; i < 8; i++)
        #pragma unroll
        for (int j = 0; j < 4; j++) acc2[i][j] = 0ULL;
    int lr = tid >> 1, lk = (tid & 1) * 4;

    for (int kk = 0; kk < K; kk += 8) {
        const float* Ap; int kc;
        if (kk < K0) { Ap = Ab; kc = kk; } else { Ap = A1; kc = kk - K0; }
        float4 av = *(const float4*)(Ap + (size_t)(mBase + lr) * K0 + kc + lk);
        float4 wv = make_float4(0.f,0.f,0.f,0.f);
        int wrow = nBase + lr;
        if (wrow < N) wv = *(const float4*)(Wb + (size_t)wrow * K + kk + lk);
        __syncthreads();
        As[lk+0][lr]=av.x; As[lk+1][lr]=av.y; As[lk+2][lr]=av.z; As[lk+3][lr]=av.w;
        Bs[lk+0][lr]=wv.x; Bs[lk+1][lr]=wv.y; Bs[lk+2][lr]=wv.z; Bs[lk+3][lr]=wv.w;
        __syncthreads();
        #pragma unroll
        for (int k = 0; k < 8; k++) {
            float4 a0 = *(float4*)&As[k][ty*8], a1 = *(float4*)&As[k][ty*8+4];
            ulonglong2 bA = *(ulonglong2*)&Bs[k][tx*8];
            ulonglong2 bB = *(ulonglong2*)&Bs[k][tx*8+4];
            float ar[8] = {a0.x,a0.y,a0.z,a0.w,a1.x,a1.y,a1.z,a1.w};
            #pragma unroll
            for (int i = 0; i < 8; i++) {
                unsigned long long ad = pack2(ar[i], ar[i]);
                acc2[i][0] = fma2(ad, bA.x, acc2[i][0]);
                acc2[i][1] = fma2(ad, bA.y, acc2[i][1]);
                acc2[i][2] = fma2(ad, bB.x, acc2[i][2]);
                acc2[i][3] = fma2(ad, bB.y, acc2[i][3]);
            }
        }
    }
    #pragma unroll
    for (int i = 0; i < 8; i++) {
        int row = mBase + ty*8 + i;
        float mk = 1.0f;
        if (epi != 0) mk = mask[row];
        #pragma unroll
        for (int jp = 0; jp < 4; jp++) {
            float2 cp = unpack2(acc2[i][jp]);
            float vv[2] = {cp.x, cp.y};
            #pragma unroll
            for (int q = 0; q < 2; q++) {
                int col = nBase + tx*8 + jp*2 + q;
                if (col < N) {
                    float v = vv[q] * scale;
                    if (bias) v += bias[col];
                    if (epi == 1) v = tanhf(v) * mk;
                    else if (epi == 2) v = v * mk;
                    Cb[(size_t)row * N + col] = v;
                }
            }
        }
    }
}

// batched C = A @ B
__global__ void __launch_bounds__(256) gemm_nn(
    const float* __restrict__ A, const float* __restrict__ Bm,
    float* __restrict__ C, int K, int N,
    size_t sA, size_t sB, size_t sC)
{
    __shared__ __align__(16) float As[8][128];
    __shared__ __align__(16) float Bs[8][128];
    int bz = blockIdx.z;
    const float* Ab = A  + (size_t)bz * sA;
    const float* Bb = Bm + (size_t)bz * sB;
    float* Cb       = C  + (size_t)bz * sC;
    int mBase = blockIdx.y * 128, nBase = blockIdx.x * 128;
    int tid = threadIdx.x, tx = tid & 15, ty = tid >> 4;
    unsigned long long acc2[8][4];
    #pragma unroll
    for (int i = 0; i < 8; i++)
        #pragma unroll
        for (int j = 0; j < 4; j++) acc2[i][j] = 0ULL;
    int alr = tid >> 1, alk = (tid & 1) * 4;
    int bkr = tid >> 5, bnc = (tid & 31) * 4;

    for (int kk = 0; kk < K; kk += 8) {
        float4 av = *(const float4*)(Ab + (size_t)(mBase + alr) * K + kk + alk);
        float4 bv = *(const float4*)(Bb + (size_t)(kk + bkr) * N + nBase + bnc);
        __syncthreads();
        As[alk+0][alr]=av.x; As[alk+1][alr]=av.y; As[alk+2][alr]=av.z; As[alk+3][alr]=av.w;
        *(float4*)&Bs[bkr][bnc] = bv;
        __syncthreads();
        #pragma unroll
        for (int k = 0; k < 8; k++) {
            float4 a0 = *(float4*)&As[k][ty*8], a1 = *(float4*)&As[k][ty*8+4];
            ulonglong2 bA = *(ulonglong2*)&Bs[k][tx*8];
            ulonglong2 bB = *(ulonglong2*)&Bs[k][tx*8+4];
            float ar[8] = {a0.x,a0.y,a0.z,a0.w,a1.x,a1.y,a1.z,a1.w};
            #pragma unroll
            for (int i = 0; i < 8; i++) {
                unsigned long long ad = pack2(ar[i], ar[i]);
                acc2[i][0] = fma2(ad, bA.x, acc2[i][0]);
                acc2[i][1] = fma2(ad, bA.y, acc2[i][1]);
                acc2[i][2] = fma2(ad, bB.x, acc2[i][2]);
                acc2[i][3] = fma2(ad, bB.y, acc2[i][3]);
            }
        }
    }
    #pragma unroll
    for (int i = 0; i < 8; i++) {
        int row = mBase + ty*8 + i;
        #pragma unroll
        for (int jp = 0; jp < 4; jp++) {
            float2 cp = unpack2(acc2[i][jp]);
            Cb[(size_t)row * N + nBase + tx*8 + jp*2 + 0] = cp.x;
            Cb[(size_t)row * N + nBase + tx*8 + jp*2 + 1] = cp.y;
        }
    }
}

// ---- per-m-group barrier: 16 blocks each, 8 groups ----
__device__ __forceinline__ void bar_mb(int mb) {
    __syncthreads();
    if (threadIdx.x == 0) {
        __threadfence();
        unsigned gen = g_gen8[mb];
        unsigned old = atomicAdd(&g_cnt8[mb], 1);
        if (old == 15u) {
            atomicExch(&g_cnt8[mb], 0u);
            __threadfence();
            g_gen8[mb] = gen + 1u;
        } else {
            while (g_gen8[mb] == gen) { }
        }
        __threadfence();
    }
    __syncthreads();
}

// persistent per-layer GRU: 128 blocks (16 j-tiles x 8 m-tiles), 256 threads.
// warp = (wj in 0..3, mg in 0..1); lane = (j_sub in 0..7, m_sub in 0..3); 2 m-rows/lane.
#define WS_LD 516
#define HS_LD 516
#define GRU_SMEM ((3*32*WS_LD + 16*HS_LD) * 4)
__global__ void __launch_bounds__(256, 1) gru_layer(
    float* __restrict__ hA, float* __restrict__ hB,
    const float* __restrict__ W, const float* __restrict__ bhh,
    const float* __restrict__ xp, float* __restrict__ y)
{
    extern __shared__ float sm[];
    float* ws = sm;                    // [3*32][WS_LD]
    float* hs = sm + 3 * 32 * WS_LD;   // [16][HS_LD]
    int tid = threadIdx.x;
    int lane = tid & 31, w = tid >> 5;
    int wj = w & 3, mg = w >> 2;
    int j_sub = lane >> 2, m_sub = lane & 3;
    int jb = blockIdx.x & 15, mb = blockIdx.x >> 4;
    int jBase = jb * 32, mBase = mb * 16;
    int j_loc = wj * 8 + j_sub;
    int j = jBase + j_loc;
    int m0_loc = mg * 8 + m_sub * 2;

    // stage W_hh slice (96 rows x 512 floats) once
    for (int idx = tid; idx < 96 * 128; idx += 256) {
        int rr = idx >> 7, c = idx & 127;
        int g = rr >> 5, jr = rr & 31;
        float4 v = *(const float4*)(W + (size_t)(g * DD + jBase + jr) * DD + c * 4);
        *(float4*)&ws[rr * WS_LD + c * 4] = v;
    }
    float brv = bhh[j], bzv = bhh[DD + j], bnv = bhh[2 * DD + j];
    const float* wp0 = &ws[(0 * 32 + j_loc) * WS_LD];
    const float* wp1 = &ws[(1 * 32 + j_loc) * WS_LD];
    const float* wp2 = &ws[(2 * 32 + j_loc) * WS_LD];
    const float* hp0 = &hs[(m0_loc + 0) * HS_LD];
    const float* hp1 = &hs[(m0_loc + 1) * HS_LD];

    for (int t = 0; t < NS; t++) {
        const float* hin  = (t & 1) ? hB : hA;
        float*       hout = (t & 1) ? hA : hB;
        // stage h tile (16 x 512)
        #pragma unroll
        for (int it = 0; it < 8; it++) {
            int idx = it * 256 + tid;
            int r = idx >> 7, c = idx & 127;
            *(float4*)&hs[r * HS_LD + c * 4] =
                *(const float4*)(hin + (size_t)(mBase + r) * DD + c * 4);
        }
        __syncthreads();

        unsigned long long a0r = 0, a0z = 0, a0n = 0, a1r = 0, a1z = 0, a1n = 0;
        #pragma unroll 8
        for (int k = 0; k < DD; k += 4) {
            ulonglong2 w0 = *(const ulonglong2*)(wp0 + k);
            ulonglong2 w1 = *(const ulonglong2*)(wp1 + k);
            ulonglong2 w2 = *(const ulonglong2*)(wp2 + k);
            ulonglong2 h0 = *(const ulonglong2*)(hp0 + k);
            ulonglong2 h1 = *(const ulonglong2*)(hp1 + k);
            a0r = fma2(h0.x, w0.x, a0r); a0r = fma2(h0.y, w0.y, a0r);
            a0z = fma2(h0.x, w1.x, a0z); a0z = fma2(h0.y, w1.y, a0z);
            a0n = fma2(h0.x, w2.x, a0n); a0n = fma2(h0.y, w2.y, a0n);
            a1r = fma2(h1.x, w0.x, a1r); a1r = fma2(h1.y, w0.y, a1r);
            a1z = fma2(h1.x, w1.x, a1z); a1z = fma2(h1.y, w1.y, a1z);
            a1n = fma2(h1.x, w2.x, a1n); a1n = fma2(h1.y, w2.y, a1n);
        }
        #pragma unroll
        for (int rsub = 0; rsub < 2; rsub++) {
            float2 pr = unpack2(rsub ? a1r : a0r);
            float2 pz = unpack2(rsub ? a1z : a0z);
            float2 pn = unpack2(rsub ? a1n : a0n);
            float gr = pr.x + pr.y, gz = pz.x + pz.y, gn = pn.x + pn.y;
            int m = mBase + m0_loc + rsub;
            size_t base = ((size_t)m * NS + t) * D3;
            float xr = xp[base + j], xz = xp[base + DD + j], xn = xp[base + 2 * DD + j];
            float r = sigmoid_fast(xr + gr + brv);
            float z = sigmoid_fast(xz + gz + bzv);
            float n = tanh_fast(xn + r * (gn + bnv));
            float hprev = hs[(m0_loc + rsub) * HS_LD + j];
            float h2 = (1.0f - z) * n + z * hprev;
            hout[(size_t)m * DD + j] = h2;
            y[((size_t)m * NS + t) * DD + j] = h2;
        }
        bar_mb(mb);
    }
}

extern "C" void kernel_launch(void* const* d_in, const int* in_sizes, int n_in,
                              void* d_out, int out_size) {
    const int*   seqs  = (const int*)d_in[0];
    const float* enc   = (const float*)d_in[2];
    const float* h0    = (const float*)d_in[3];
    const float* emb   = (const float*)d_in[4];
    const float* w_ih  = (const float*)d_in[5];
    const float* w_hh  = (const float*)d_in[6];
    const float* b_ih  = (const float*)d_in[7];
    const float* b_hh  = (const float*)d_in[8];
    const float* attnw = (const float*)d_in[9];
    const float* attnb = (const float*)d_in[10];
    const float* outw  = (const float*)d_in[11];
    const float* outb  = (const float*)d_in[12];
    float* out = (float*)d_out;

    float *xbuf, *xp, *ctx, *hA, *hB, *mask;
    cudaGetSymbolAddress((void**)&xbuf, g_xbuf);
    cudaGetSymbolAddress((void**)&xp,   g_xp);
    cudaGetSymbolAddress((void**)&ctx,  g_ctx);
    cudaGetSymbolAddress((void**)&hA,   g_hA);
    cudaGetSymbolAddress((void**)&hB,   g_hB);
    cudaGetSymbolAddress((void**)&mask, g_mask);

    static int smem_set = 0;
    if (!smem_set) {
        cudaFuncSetAttribute(gru_layer, cudaFuncAttributeMaxDynamicSharedMemorySize, GRU_SMEM);
        smem_set = 1;
    }

    const size_t OUT_H    = (size_t)MALL * NV;
    const size_t OUT_ATTN = OUT_H + (size_t)NL * NB * DD;
    float* attnP = out + OUT_ATTN;

    embed_kernel<<<(MALL * (DD/4)) / 256, 256>>>(seqs, emb, xbuf);

    for (int l = 0; l < NL; l++) {
        gemm_nt<<<dim3(D3/128, MALL/128, 1), 256>>>(
            xbuf, nullptr, DD, DD,
            w_ih + (size_t)l * D3 * DD, b_ih + (size_t)l * D3,
            xp, D3, 0, 0, 0, 1.0f, nullptr, 0);
        copy4_kernel<<<64, 256>>>(hA, h0 + (size_t)l * NB * DD, NB * DD / 4);
        gru_layer<<<128, 256, GRU_SMEM>>>(
            hA, hB, w_hh + (size_t)l * D3 * DD, b_hh + (size_t)l * D3, xp, xbuf);
        copy4_kernel<<<64, 256>>>(out + OUT_H + (size_t)l * NB * DD, hA, NB * DD / 4);
    }

    mask_kernel<<<MALL / 256, 256>>>(xbuf, mask);

    gemm_nt<<<dim3(NSE/128, NS/128, NB), 256>>>(
        xbuf, nullptr, DD, DD, enc, nullptr,
        attnP, NSE,
        (size_t)NS * DD, (size_t)NSE * DD, (size_t)NS * NSE,
        0.044194173824159216f, nullptr, 0);
    softmax_kernel<<<MALL, 256>>>(attnP);

    gemm_nn<<<dim3(DD/128, NS/128, NB), 256>>>(
        attnP, enc, ctx, NSE, DD,
        (size_t)NS * NSE, (size_t)NSE * DD, (size_t)NS * DD);

    gemm_nt<<<dim3(DD/128, MALL/128, 1), 256>>>(
        xbuf, ctx, DD, 2 * DD, attnw, attnb,
        xp, DD, 0, 0, 0, 1.0f, mask, 1);

    gemm_nt<<<dim3(1, MALL/128, 1), 256>>>(
        xp, nullptr, DD, DD, outw, outb,
        out, NV, 0, 0, 0, 1.0f, mask, 2);
}

// round 7
// speedup vs baseline: 1.2408x; 1.2287x over previous
#include <cuda_runtime.h>
#include <cuda_bf16.h>
#include <math.h>
#include <stdint.h>

#define NL 3
#define DD 512
#define NV 100
#define NB 128
#define NS 512
#define NSE 512
#define MALL (NB*NS)
#define D3 (3*DD)

// ---------------- scratch ----------------
__device__ float g_xbuf[(size_t)MALL * DD];
__device__ float g_xp[(size_t)MALL * D3];     // xp transposed [m][3D][t]; later reused plain for attn_masked
__device__ float g_ctx[(size_t)MALL * DD];
__device__ float g_hA[NB * DD];
__device__ float g_hB[NB * DD];
__device__ float g_mask[MALL];
__device__ unsigned g_cnt8[8];
__device__ volatile unsigned g_gen8[8];
// bf16 split buffers
__device__ __nv_bfloat16 g_Ah[(size_t)MALL * DD];
__device__ __nv_bfloat16 g_Al[(size_t)MALL * DD];
__device__ __nv_bfloat16 g_Bh[(size_t)MALL * DD];
__device__ __nv_bfloat16 g_Bl[(size_t)MALL * DD];
__device__ __nv_bfloat16 g_ench[(size_t)NB * NSE * DD];
__device__ __nv_bfloat16 g_encl[(size_t)NB * NSE * DD];
__device__ __nv_bfloat16 g_encTh[(size_t)NB * DD * NSE];
__device__ __nv_bfloat16 g_encTl[(size_t)NB * DD * NSE];
__device__ __nv_bfloat16 g_wihh[(size_t)NL * D3 * DD];
__device__ __nv_bfloat16 g_wihl[(size_t)NL * D3 * DD];
__device__ __nv_bfloat16 g_awh[(size_t)DD * 2 * DD];
__device__ __nv_bfloat16 g_awl[(size_t)DD * 2 * DD];
__device__ __nv_bfloat16 g_owh[128 * DD];
__device__ __nv_bfloat16 g_owl[128 * DD];

// single extern shared symbol
extern __shared__ float smf[];

// ---------------- helpers ----------------
__device__ __forceinline__ unsigned long long fma2(unsigned long long a, unsigned long long b, unsigned long long c) {
    unsigned long long d;
    asm("fma.rn.f32x2 %0, %1, %2, %3;" : "=l"(d) : "l"(a), "l"(b), "l"(c));
    return d;
}
__device__ __forceinline__ float2 unpack2(unsigned long long v) {
    float2 r;
    asm("mov.b64 {%0, %1}, %2;" : "=f"(r.x), "=f"(r.y) : "l"(v));
    return r;
}
__device__ __forceinline__ float tanh_fast(float x) {
    float y;
    asm("tanh.approx.f32 %0, %1;" : "=f"(y) : "f"(x));
    return y;
}
__device__ __forceinline__ float sigmoid_fast(float x) { return 1.0f / (1.0f + __expf(-x)); }

__device__ __forceinline__ uint32_t smem_u32(const void* p) {
    uint32_t a;
    asm("{ .reg .u64 t; cvta.to.shared.u64 t, %1; cvt.u32.u64 %0, t; }" : "=r"(a) : "l"(p));
    return a;
}

// ---------------- mma.sync primitives (baseline sm_80+, works on sm_103) ----------------
__device__ __forceinline__ void mma16816(float* d, const uint32_t* a, const uint32_t* b) {
    asm volatile(
        "mma.sync.aligned.m16n8k16.row.col.f32.bf16.bf16.f32 "
        "{%0,%1,%2,%3}, {%4,%5,%6,%7}, {%8,%9}, {%0,%1,%2,%3};"
        : "+f"(d[0]), "+f"(d[1]), "+f"(d[2]), "+f"(d[3])
        : "r"(a[0]), "r"(a[1]), "r"(a[2]), "r"(a[3]), "r"(b[0]), "r"(b[1]));
}
__device__ __forceinline__ void ldsm_x4(uint32_t* r, uint32_t addr) {
    asm volatile("ldmatrix.sync.aligned.m8n8.x4.shared.b16 {%0,%1,%2,%3}, [%4];"
        : "=r"(r[0]), "=r"(r[1]), "=r"(r[2]), "=r"(r[3]) : "r"(addr));
}
__device__ __forceinline__ void cpasync16(uint32_t dst, const void* src, int sz) {
    asm volatile("cp.async.ca.shared.global [%0], [%1], 16, %2;" :: "r"(dst), "l"(src), "r"(sz) : "memory");
}
#define CP_COMMIT() asm volatile("cp.async.commit_group;" ::: "memory")
#define CP_WAIT1()  asm volatile("cp.async.wait_group 1;" ::: "memory")
#define CP_WAIT0()  asm volatile("cp.async.wait_group 0;" ::: "memory")

// ---------------- small kernels ----------------
__global__ void embed_kernel(const int* __restrict__ seqs, const float* __restrict__ emb, float* __restrict__ xbuf) {
    size_t i = (size_t)blockIdx.x * blockDim.x + threadIdx.x;
    size_t row = i >> 7;
    int c = (int)(i & 127);
    int tok = seqs[row];
    ((float4*)xbuf)[i] = ((const float4*)(emb + (size_t)tok * DD))[c];
}
__global__ void copy4_kernel(float* __restrict__ dst, const float* __restrict__ src, int n4) {
    int i = blockIdx.x * blockDim.x + threadIdx.x;
    if (i < n4) ((float4*)dst)[i] = ((const float4*)src)[i];
}
__global__ void mask_kernel(const float* __restrict__ xbuf, float* __restrict__ maskp) {
    int m = blockIdx.x * blockDim.x + threadIdx.x;
    if (m < MALL) maskp[m] = (xbuf[(size_t)m * DD] != 0.0f) ? 1.0f : 0.0f;
}
__global__ void softmax_kernel(float* __restrict__ P) {
    __shared__ float red[256];
    float* p = P + (size_t)blockIdx.x * NSE;
    int tid = threadIdx.x;
    float v0 = p[tid], v1 = p[tid + 256];
    red[tid] = fmaxf(v0, v1); __syncthreads();
    #pragma unroll
    for (int s = 128; s > 0; s >>= 1) { if (tid < s) red[tid] = fmaxf(red[tid], red[tid + s]); __syncthreads(); }
    float mx = red[0]; __syncthreads();
    float e0 = __expf(v0 - mx), e1 = __expf(v1 - mx);
    red[tid] = e0 + e1; __syncthreads();
    #pragma unroll
    for (int s = 128; s > 0; s >>= 1) { if (tid < s) red[tid] += red[tid + s]; __syncthreads(); }
    float inv = 1.0f / red[0];
    p[tid] = e0 * inv; p[tid + 256] = e1 * inv;
}

__device__ __forceinline__ unsigned bfu(__nv_bfloat16 b) {
    unsigned short s = __bfloat16_as_ushort(b);
    return (unsigned)s;
}
__global__ void split4_kernel(const float* __restrict__ s, __nv_bfloat16* __restrict__ h,
                              __nv_bfloat16* __restrict__ l, int n4) {
    int i = blockIdx.x * 256 + threadIdx.x;
    if (i >= n4) return;
    float4 v = ((const float4*)s)[i];
    __nv_bfloat16 h0 = __float2bfloat16_rn(v.x), h1 = __float2bfloat16_rn(v.y);
    __nv_bfloat16 h2 = __float2bfloat16_rn(v.z), h3 = __float2bfloat16_rn(v.w);
    __nv_bfloat16 l0 = __float2bfloat16_rn(v.x - __bfloat162float(h0));
    __nv_bfloat16 l1 = __float2bfloat16_rn(v.y - __bfloat162float(h1));
    __nv_bfloat16 l2 = __float2bfloat16_rn(v.z - __bfloat162float(h2));
    __nv_bfloat16 l3 = __float2bfloat16_rn(v.w - __bfloat162float(h3));
    uint2 hv, lv;
    hv.x = bfu(h0) | (bfu(h1) << 16); hv.y = bfu(h2) | (bfu(h3) << 16);
    lv.x = bfu(l0) | (bfu(l1) << 16); lv.y = bfu(l2) | (bfu(l3) << 16);
    ((uint2*)h)[i] = hv; ((uint2*)l)[i] = lv;
}
__global__ void splitpad_kernel(const float* __restrict__ s, __nv_bfloat16* __restrict__ h,
                                __nv_bfloat16* __restrict__ l) {
    int i = blockIdx.x * 256 + threadIdx.x;
    if (i >= 128 * DD) return;
    int r = i / DD, c = i % DD;
    float v = (r < NV) ? s[r * DD + c] : 0.0f;
    __nv_bfloat16 hb = __float2bfloat16_rn(v);
    h[i] = hb;
    l[i] = __float2bfloat16_rn(v - __bfloat162float(hb));
}
__global__ void transpose_split_kernel(const float* __restrict__ enc,
                                       __nv_bfloat16* __restrict__ th, __nv_bfloat16* __restrict__ tl) {
    __shared__ float tile[32][33];
    int b = blockIdx.z;
    int d0 = blockIdx.x * 32, s0 = blockIdx.y * 32;
    int x = threadIdx.x, y = threadIdx.y;
    #pragma unroll
    for (int i = 0; i < 32; i += 8)
        tile[y + i][x] = enc[((size_t)b * NSE + s0 + y + i) * DD + d0 + x];
    __syncthreads();
    #pragma unroll
    for (int i = 0; i < 32; i += 8) {
        float v = tile[x][y + i];
        __nv_bfloat16 hb = __float2bfloat16_rn(v);
        size_t o = ((size_t)b * DD + d0 + y + i) * NSE + s0 + x;
        th[o] = hb;
        tl[o] = __float2bfloat16_rn(v - __bfloat162float(hb));
    }
}

// ---------------- mma.sync split-bf16 NT GEMM ----------------
// C[m,n] = scale*sum_k A[m,k]*W[n,k] + bias[n].  Tile 128x128, BK=32, 8 warps (2m x 4n).
// A = [A0|A1] concat at K0 (A1 ld = K1). B rows >= nvalid zero-filled.
// epi: 0 none, 1 tanh*mask, 2 *mask, 3 xp-transposed store
#define LDT 40                       // 32 + 8 pad (bf16 elems per row)
#define TILE_B (128 * LDT * 2)       // 10240 bytes per tile
#define STAGE_B (4 * TILE_B)         // 40960
#define GM_SMEM (2 * STAGE_B)        // 81920
__global__ void __launch_bounds__(256, 1) gemm_mma(
    const __nv_bfloat16* __restrict__ A0h, const __nv_bfloat16* __restrict__ A0l,
    const __nv_bfloat16* __restrict__ A1h, const __nv_bfloat16* __restrict__ A1l,
    int K0, int K1, int K,
    const __nv_bfloat16* __restrict__ Wh, const __nv_bfloat16* __restrict__ Wl, int nvalid,
    float* __restrict__ C, int ldc,
    size_t sA, size_t sW, size_t sC,
    float scale, const float* __restrict__ bias, const float* __restrict__ mask, int epi)
{
    uint32_t smb = smem_u32(smf);
    int tid = threadIdx.x, lane = tid & 31, wid = tid >> 5;
    int wm = wid >> 2, wn = wid & 3;
    int bz = blockIdx.z;
    int nBase = blockIdx.x * 128, mBase = blockIdx.y * 128;
    const __nv_bfloat16* a0h = A0h + (size_t)bz * sA;
    const __nv_bfloat16* a0l = A0l + (size_t)bz * sA;
    const __nv_bfloat16* wh  = Wh  + (size_t)bz * sW;
    const __nv_bfloat16* wl  = Wl  + (size_t)bz * sW;
    float* Cb = C + (size_t)bz * sC;

    float acc[4][4][4];
    #pragma unroll
    for (int i = 0; i < 4; i++)
        #pragma unroll
        for (int j = 0; j < 4; j++)
            #pragma unroll
            for (int q = 0; q < 4; q++) acc[i][j][q] = 0.0f;

    auto load_chunk = [&](int buf, int c) {
        int kOff = c * 32;
        const __nv_bfloat16 *ah, *al;
        int lda, ka;
        if (kOff < K0) { ah = a0h; al = a0l; lda = K0; ka = kOff; }
        else           { ah = A1h; al = A1l; lda = K1; ka = kOff - K0; }
        uint32_t sb = smb + buf * STAGE_B;
        #pragma unroll
        for (int p = 0; p < 8; p++) {
            int idx = p * 256 + tid;
            int tile = idx >> 9, rem = idx & 511;
            int r = rem >> 2, c16 = rem & 3;
            uint32_t dst = sb + tile * TILE_B + r * (LDT * 2) + c16 * 16;
            if (tile == 0)      cpasync16(dst, ah + (size_t)(mBase + r) * lda + ka + c16 * 8, 16);
            else if (tile == 1) cpasync16(dst, al + (size_t)(mBase + r) * lda + ka + c16 * 8, 16);
            else if (tile == 2) cpasync16(dst, wh + (size_t)(nBase + r) * K + kOff + c16 * 8, (nBase + r < nvalid) ? 16 : 0);
            else                cpasync16(dst, wl + (size_t)(nBase + r) * K + kOff + c16 * 8, (nBase + r < nvalid) ? 16 : 0);
        }
    };

    int aRow = lane & 15, aK = (lane >> 4) * 8;
    int bRow = (lane & 7) + ((lane >> 4) & 1) * 8, bK = ((lane >> 3) & 1) * 8;

    int nk = K / 32;
    load_chunk(0, 0);
    CP_COMMIT();
    for (int c = 0; c < nk; c++) {
        if (c + 1 < nk) { load_chunk((c + 1) & 1, c + 1); CP_COMMIT(); CP_WAIT1(); }
        else            { CP_WAIT0(); }
        __syncthreads();
        uint32_t sb = smb + (c & 1) * STAGE_B;
        #pragma unroll
        for (int ks = 0; ks < 2; ks++) {
            uint32_t ahf[4][4], alf[4][4], bhf[4][2], blf[4][2];
            #pragma unroll
            for (int mf = 0; mf < 4; mf++) {
                uint32_t ra = sb + ((wm * 64 + mf * 16 + aRow) * LDT + ks * 16 + aK) * 2;
                ldsm_x4(ahf[mf], ra);
                ldsm_x4(alf[mf], ra + TILE_B);
            }
            #pragma unroll
            for (int np = 0; np < 2; np++) {
                uint32_t rb = sb + 2 * TILE_B + ((wn * 32 + np * 16 + bRow) * LDT + ks * 16 + bK) * 2;
                uint32_t tmp[4];
                ldsm_x4(tmp, rb);
                bhf[np * 2][0] = tmp[0]; bhf[np * 2][1] = tmp[1];
                bhf[np * 2 + 1][0] = tmp[2]; bhf[np * 2 + 1][1] = tmp[3];
                ldsm_x4(tmp, rb + TILE_B);
                blf[np * 2][0] = tmp[0]; blf[np * 2][1] = tmp[1];
                blf[np * 2 + 1][0] = tmp[2]; blf[np * 2 + 1][1] = tmp[3];
            }
            #pragma unroll
            for (int mf = 0; mf < 4; mf++)
                #pragma unroll
                for (int nf = 0; nf < 4; nf++) {
                    mma16816(acc[mf][nf], ahf[mf], bhf[nf]);
                    mma16816(acc[mf][nf], ahf[mf], blf[nf]);
                    mma16816(acc[mf][nf], alf[mf], bhf[nf]);
                }
        }
        __syncthreads();
    }

    // epilogue: thread holds (row0 = base + lane/4, row1 = row0+8) x (col = cbase + (lane%4)*2, col+1)
    int rOff = lane >> 2, cOff = (lane & 3) * 2;
    #pragma unroll
    for (int mf = 0; mf < 4; mf++) {
        int mrow0 = mBase + wm * 64 + mf * 16 + rOff;
        int mrow1 = mrow0 + 8;
        float mk0 = 1.0f, mk1 = 1.0f;
        if (epi == 1 || epi == 2) { mk0 = mask[mrow0]; mk1 = mask[mrow1]; }
        #pragma unroll
        for (int nf = 0; nf < 4; nf++) {
            int col = nBase + wn * 32 + nf * 8 + cOff;
            if (col >= nvalid && epi != 3) continue;
            float v0 = acc[mf][nf][0] * scale, v1 = acc[mf][nf][1] * scale;
            float v2 = acc[mf][nf][2] * scale, v3 = acc[mf][nf][3] * scale;
            if (bias) {
                float b0 = bias[col], b1 = bias[col + 1];
                v0 += b0; v1 += b1; v2 += b0; v3 += b1;
            }
            if (epi == 3) {
                int mm0 = mrow0 >> 9, tt0 = mrow0 & 511;
                int mm1 = mrow1 >> 9, tt1 = mrow1 & 511;
                Cb[((size_t)mm0 * D3 + col) * NS + tt0] = v0;
                Cb[((size_t)mm0 * D3 + col + 1) * NS + tt0] = v1;
                Cb[((size_t)mm1 * D3 + col) * NS + tt1] = v2;
                Cb[((size_t)mm1 * D3 + col + 1) * NS + tt1] = v3;
            } else {
                if (epi == 1) {
                    v0 = tanh_fast(v0) * mk0; v1 = tanh_fast(v1) * mk0;
                    v2 = tanh_fast(v2) * mk1; v3 = tanh_fast(v3) * mk1;
                } else if (epi == 2) {
                    v0 *= mk0; v1 *= mk0; v2 *= mk1; v3 *= mk1;
                }
                *(float2*)(Cb + (size_t)mrow0 * ldc + col) = make_float2(v0, v1);
                *(float2*)(Cb + (size_t)mrow1 * ldc + col) = make_float2(v2, v3);
            }
        }
    }
}

// ---------------- per-m-group barrier ----------------
__device__ __forceinline__ void bar_mb(int mb) {
    __syncthreads();
    if (threadIdx.x == 0) {
        __threadfence();
        unsigned gen = g_gen8[mb];
        unsigned old = atomicAdd(&g_cnt8[mb], 1);
        if (old == 15u) {
            atomicExch(&g_cnt8[mb], 0u);
            __threadfence();
            g_gen8[mb] = gen + 1u;
        } else {
            while (g_gen8[mb] == gen) { }
        }
        __threadfence();
    }
    __syncthreads();
}

// persistent per-layer GRU: 128 blocks (16 j x 8 m), 256 threads. xp is transposed [m][3D][t].
#define WS_LD 516
#define HS_LD 516
#define GRU_SMEM ((3*32*WS_LD + 16*HS_LD) * 4)
__global__ void __launch_bounds__(256, 1) gru_layer(
    float* __restrict__ hA, float* __restrict__ hB,
    const float* __restrict__ W, const float* __restrict__ bhh,
    const float* __restrict__ xpT, float* __restrict__ y)
{
    float* ws = smf;
    float* hs = smf + 3 * 32 * WS_LD;
    int tid = threadIdx.x;
    int lane = tid & 31, w = tid >> 5;
    int wj = w & 3, mg = w >> 2;
    int j_sub = lane >> 2, m_sub = lane & 3;
    int jb = blockIdx.x & 15, mb = blockIdx.x >> 4;
    int jBase = jb * 32, mBase = mb * 16;
    int j_loc = wj * 8 + j_sub;
    int j = jBase + j_loc;
    int m0_loc = mg * 8 + m_sub * 2;

    for (int idx = tid; idx < 96 * 128; idx += 256) {
        int rr = idx >> 7, c = idx & 127;
        int g = rr >> 5, jr = rr & 31;
        float4 v = *(const float4*)(W + (size_t)(g * DD + jBase + jr) * DD + c * 4);
        *(float4*)&ws[rr * WS_LD + c * 4] = v;
    }
    float brv = bhh[j], bzv = bhh[DD + j], bnv = bhh[2 * DD + j];
    const float* wp0 = &ws[(0 * 32 + j_loc) * WS_LD];
    const float* wp1 = &ws[(1 * 32 + j_loc) * WS_LD];
    const float* wp2 = &ws[(2 * 32 + j_loc) * WS_LD];
    const float* hp0 = &hs[(m0_loc + 0) * HS_LD];
    const float* hp1 = &hs[(m0_loc + 1) * HS_LD];
    int m0g = mBase + m0_loc, m1g = m0g + 1;
    const float* xr0p = xpT + ((size_t)m0g * D3 + j) * NS;
    const float* xr1p = xpT + ((size_t)m1g * D3 + j) * NS;

    for (int t = 0; t < NS; t++) {
        const float* hin  = (t & 1) ? hB : hA;
        float*       hout = (t & 1) ? hA : hB;
        #pragma unroll
        for (int it = 0; it < 8; it++) {
            int idx = it * 256 + tid;
            int r = idx >> 7, c = idx & 127;
            *(float4*)&hs[r * HS_LD + c * 4] =
                *(const float4*)(hin + (size_t)(mBase + r) * DD + c * 4);
        }
        __syncthreads();

        unsigned long long a0r = 0, a0z = 0, a0n = 0, a1r = 0, a1z = 0, a1n = 0;
        #pragma unroll 8
        for (int k = 0; k < DD; k += 4) {
            ulonglong2 w0 = *(const ulonglong2*)(wp0 + k);
            ulonglong2 w1 = *(const ulonglong2*)(wp1 + k);
            ulonglong2 w2 = *(const ulonglong2*)(wp2 + k);
            ulonglong2 h0 = *(const ulonglong2*)(hp0 + k);
            ulonglong2 h1 = *(const ulonglong2*)(hp1 + k);
            a0r = fma2(h0.x, w0.x, a0r); a0r = fma2(h0.y, w0.y, a0r);
            a0z = fma2(h0.x, w1.x, a0z); a0z = fma2(h0.y, w1.y, a0z);
            a0n = fma2(h0.x, w2.x, a0n); a0n = fma2(h0.y, w2.y, a0n);
            a1r = fma2(h1.x, w0.x, a1r); a1r = fma2(h1.y, w0.y, a1r);
            a1z = fma2(h1.x, w1.x, a1z); a1z = fma2(h1.y, w1.y, a1z);
            a1n = fma2(h1.x, w2.x, a1n); a1n = fma2(h1.y, w2.y, a1n);
        }
        #pragma unroll
        for (int rsub = 0; rsub < 2; rsub++) {
            float2 pr = unpack2(rsub ? a1r : a0r);
            float2 pz = unpack2(rsub ? a1z : a0z);
            float2 pn = unpack2(rsub ? a1n : a0n);
            float gr = pr.x + pr.y, gz = pz.x + pz.y, gn = pn.x + pn.y;
            int m = rsub ? m1g : m0g;
            const float* xq = rsub ? xr1p : xr0p;
            float xr = xq[t], xz = xq[(size_t)DD * NS + t], xn = xq[(size_t)2 * DD * NS + t];
            float r = sigmoid_fast(xr + gr + brv);
            float z = sigmoid_fast(xz + gz + bzv);
            float n = tanh_fast(xn + r * (gn + bnv));
            float hprev = hs[(m0_loc + rsub) * HS_LD + j];
            float h2 = (1.0f - z) * n + z * hprev;
            hout[(size_t)m * DD + j] = h2;
            y[((size_t)m * NS + t) * DD + j] = h2;
        }
        bar_mb(mb);
    }
}

extern "C" void kernel_launch(void* const* d_in, const int* in_sizes, int n_in,
                              void* d_out, int out_size) {
    const int*   seqs  = (const int*)d_in[0];
    const float* enc   = (const float*)d_in[2];
    const float* h0    = (const float*)d_in[3];
    const float* emb   = (const float*)d_in[4];
    const float* w_ih  = (const float*)d_in[5];
    const float* w_hh  = (const float*)d_in[6];
    const float* b_ih  = (const float*)d_in[7];
    const float* b_hh  = (const float*)d_in[8];
    const float* attnw = (const float*)d_in[9];
    const float* attnb = (const float*)d_in[10];
    const float* outw  = (const float*)d_in[11];
    const float* outb  = (const float*)d_in[12];
    float* out = (float*)d_out;

    float *xbuf, *xp, *ctx, *hA, *hB, *mask;
    __nv_bfloat16 *Ah, *Al, *Bh, *Bl, *ench, *encl, *encTh, *encTl, *wihh, *wihl, *awh, *awl, *owh, *owl;
    cudaGetSymbolAddress((void**)&xbuf, g_xbuf);
    cudaGetSymbolAddress((void**)&xp,   g_xp);
    cudaGetSymbolAddress((void**)&ctx,  g_ctx);
    cudaGetSymbolAddress((void**)&hA,   g_hA);
    cudaGetSymbolAddress((void**)&hB,   g_hB);
    cudaGetSymbolAddress((void**)&mask, g_mask);
    cudaGetSymbolAddress((void**)&Ah, g_Ah);   cudaGetSymbolAddress((void**)&Al, g_Al);
    cudaGetSymbolAddress((void**)&Bh, g_Bh);   cudaGetSymbolAddress((void**)&Bl, g_Bl);
    cudaGetSymbolAddress((void**)&ench, g_ench);   cudaGetSymbolAddress((void**)&encl, g_encl);
    cudaGetSymbolAddress((void**)&encTh, g_encTh); cudaGetSymbolAddress((void**)&encTl, g_encTl);
    cudaGetSymbolAddress((void**)&wihh, g_wihh);   cudaGetSymbolAddress((void**)&wihl, g_wihl);
    cudaGetSymbolAddress((void**)&awh, g_awh);     cudaGetSymbolAddress((void**)&awl, g_awl);
    cudaGetSymbolAddress((void**)&owh, g_owh);     cudaGetSymbolAddress((void**)&owl, g_owl);

    static int attr_set = 0;
    if (!attr_set) {
        cudaFuncSetAttribute(gru_layer, cudaFuncAttributeMaxDynamicSharedMemorySize, GRU_SMEM);
        cudaFuncSetAttribute(gemm_mma, cudaFuncAttributeMaxDynamicSharedMemorySize, GM_SMEM);
        attr_set = 1;
    }

    const size_t OUT_H    = (size_t)MALL * NV;
    const size_t OUT_ATTN = OUT_H + (size_t)NL * NB * DD;
    float* attnP = out + OUT_ATTN;
    const int NA4 = (MALL * DD) / 4;
    const float SC = 0.044194173824159216f;

    split4_kernel<<<(NL * D3 * DD / 4 + 255) / 256, 256>>>(w_ih, wihh, wihl, NL * D3 * DD / 4);
    split4_kernel<<<(DD * 2 * DD / 4 + 255) / 256, 256>>>(attnw, awh, awl, DD * 2 * DD / 4);
    splitpad_kernel<<<(128 * DD + 255) / 256, 256>>>(outw, owh, owl);
    split4_kernel<<<(NB * NSE * DD / 4 + 255) / 256, 256>>>(enc, ench, encl, NB * NSE * DD / 4);
    transpose_split_kernel<<<dim3(16, 16, 128), dim3(32, 8)>>>(enc, encTh, encTl);

    embed_kernel<<<(MALL * (DD / 4)) / 256, 256>>>(seqs, emb, xbuf);

    for (int l = 0; l < NL; l++) {
        split4_kernel<<<NA4 / 256, 256>>>(xbuf, Ah, Al, NA4);
        gemm_mma<<<dim3(12, 512, 1), 256, GM_SMEM>>>(
            Ah, Al, nullptr, nullptr, DD, DD, DD,
            wihh + (size_t)l * D3 * DD, wihl + (size_t)l * D3 * DD, D3,
            xp, 0, 0, 0, 0, 1.0f, b_ih + (size_t)l * D3, nullptr, 3);
        copy4_kernel<<<64, 256>>>(hA, h0 + (size_t)l * NB * DD, NB * DD / 4);
        gru_layer<<<128, 256, GRU_SMEM>>>(
            hA, hB, w_hh + (size_t)l * D3 * DD, b_hh + (size_t)l * D3, xp, xbuf);
        copy4_kernel<<<64, 256>>>(out + OUT_H + (size_t)l * NB * DD, hA, NB * DD / 4);
    }

    mask_kernel<<<MALL / 256, 256>>>(xbuf, mask);

    split4_kernel<<<NA4 / 256, 256>>>(xbuf, Ah, Al, NA4);

    gemm_mma<<<dim3(4, 4, 128), 256, GM_SMEM>>>(
        Ah, Al, nullptr, nullptr, DD, DD, DD,
        ench, encl, NSE,
        attnP, NSE, (size_t)NS * DD, (size_t)NSE * DD, (size_t)NS * NSE,
        SC, nullptr, nullptr, 0);
    softmax_kernel<<<MALL, 256>>>(attnP);

    split4_kernel<<<NA4 / 256, 256>>>(attnP, Bh, Bl, NA4);
    gemm_mma<<<dim3(4, 4, 128), 256, GM_SMEM>>>(
        Bh, Bl, nullptr, nullptr, NSE, NSE, NSE,
        encTh, encTl, DD,
        ctx, DD, (size_t)NS * NSE, (size_t)DD * NSE, (size_t)NS * DD,
        1.0f, nullptr, nullptr, 0);

    split4_kernel<<<NA4 / 256, 256>>>(ctx, Bh, Bl, NA4);
    gemm_mma<<<dim3(4, 512, 1), 256, GM_SMEM>>>(
        Ah, Al, Bh, Bl, DD, DD, 2 * DD,
        awh, awl, DD,
        xp, DD, 0, 0, 0, 1.0f, attnb, mask, 1);

    split4_kernel<<<NA4 / 256, 256>>>(xp, Ah, Al, NA4);
    gemm_mma<<<dim3(1, 512, 1), 256, GM_SMEM>>>(
        Ah, Al, nullptr, nullptr, DD, DD, DD,
        owh, owl, NV,
        out, NV, 0, 0, 0, 1.0f, outb, mask, 2);
}

// round 9
// speedup vs baseline: 1.2809x; 1.0323x over previous
#include <cuda_runtime.h>
#include <cuda_bf16.h>
#include <math.h>
#include <stdint.h>

#define NL 3
#define DD 512
#define NV 100
#define NB 128
#define NS 512
#define NSE 512
#define MALL (NB*NS)
#define D3 (3*DD)

// ---------------- scratch ----------------
__device__ float g_xp[(size_t)MALL * D3];     // xp transposed [m][3D][t]
__device__ float g_hA[NB * DD];
__device__ float g_hB[NB * DD];
__device__ float g_mask[MALL];
__device__ unsigned g_cnt8[8];
__device__ volatile unsigned g_gen8[8];
// bf16 split buffers
__device__ __nv_bfloat16 g_Ah[(size_t)MALL * DD];   // x / y / dec
__device__ __nv_bfloat16 g_Al[(size_t)MALL * DD];
__device__ __nv_bfloat16 g_Ph[(size_t)MALL * NSE];  // softmax probs
__device__ __nv_bfloat16 g_Pl[(size_t)MALL * NSE];
__device__ __nv_bfloat16 g_Ch[(size_t)MALL * DD];   // context
__device__ __nv_bfloat16 g_Cl[(size_t)MALL * DD];
__device__ __nv_bfloat16 g_Dh[(size_t)MALL * DD];   // attn_masked
__device__ __nv_bfloat16 g_Dl[(size_t)MALL * DD];
__device__ __nv_bfloat16 g_ench[(size_t)NB * NSE * DD];
__device__ __nv_bfloat16 g_encl[(size_t)NB * NSE * DD];
__device__ __nv_bfloat16 g_encTh[(size_t)NB * DD * NSE];
__device__ __nv_bfloat16 g_encTl[(size_t)NB * DD * NSE];
__device__ __nv_bfloat16 g_wihh[(size_t)NL * D3 * DD];
__device__ __nv_bfloat16 g_wihl[(size_t)NL * D3 * DD];
__device__ __nv_bfloat16 g_awh[(size_t)DD * 2 * DD];
__device__ __nv_bfloat16 g_awl[(size_t)DD * 2 * DD];
__device__ __nv_bfloat16 g_owh[128 * DD];
__device__ __nv_bfloat16 g_owl[128 * DD];

extern __shared__ float smf[];

// ---------------- helpers ----------------
__device__ __forceinline__ unsigned long long fma2(unsigned long long a, unsigned long long b, unsigned long long c) {
    unsigned long long d;
    asm("fma.rn.f32x2 %0, %1, %2, %3;" : "=l"(d) : "l"(a), "l"(b), "l"(c));
    return d;
}
__device__ __forceinline__ float2 unpack2(unsigned long long v) {
    float2 r;
    asm("mov.b64 {%0, %1}, %2;" : "=f"(r.x), "=f"(r.y) : "l"(v));
    return r;
}
__device__ __forceinline__ float tanh_fast(float x) {
    float y;
    asm("tanh.approx.f32 %0, %1;" : "=f"(y) : "f"(x));
    return y;
}
__device__ __forceinline__ float sigmoid_fast(float x) { return 1.0f / (1.0f + __expf(-x)); }
__device__ __forceinline__ uint32_t smem_u32(const void* p) {
    uint32_t a;
    asm("{ .reg .u64 t; cvta.to.shared.u64 t, %1; cvt.u32.u64 %0, t; }" : "=r"(a) : "l"(p));
    return a;
}
__device__ __forceinline__ unsigned bfu(__nv_bfloat16 b) {
    unsigned short s = __bfloat16_as_ushort(b);
    return (unsigned)s;
}

// ---------------- mma.sync primitives ----------------
__device__ __forceinline__ void mma16816(float* d, const uint32_t* a, const uint32_t* b) {
    asm volatile(
        "mma.sync.aligned.m16n8k16.row.col.f32.bf16.bf16.f32 "
        "{%0,%1,%2,%3}, {%4,%5,%6,%7}, {%8,%9}, {%0,%1,%2,%3};"
        : "+f"(d[0]), "+f"(d[1]), "+f"(d[2]), "+f"(d[3])
        : "r"(a[0]), "r"(a[1]), "r"(a[2]), "r"(a[3]), "r"(b[0]), "r"(b[1]));
}
__device__ __forceinline__ void ldsm_x4(uint32_t* r, uint32_t addr) {
    asm volatile("ldmatrix.sync.aligned.m8n8.x4.shared.b16 {%0,%1,%2,%3}, [%4];"
        : "=r"(r[0]), "=r"(r[1]), "=r"(r[2]), "=r"(r[3]) : "r"(addr));
}
__device__ __forceinline__ void cpasync16(uint32_t dst, const void* src, int sz) {
    asm volatile("cp.async.ca.shared.global [%0], [%1], 16, %2;" :: "r"(dst), "l"(src), "r"(sz) : "memory");
}
#define CP_COMMIT() asm volatile("cp.async.commit_group;" ::: "memory")
#define CP_WAIT2()  asm volatile("cp.async.wait_group 2;" ::: "memory")

// ---------------- small kernels ----------------
__global__ void embed_split_kernel(const int* __restrict__ seqs, const float* __restrict__ emb,
                                   __nv_bfloat16* __restrict__ h, __nv_bfloat16* __restrict__ l) {
    size_t i = (size_t)blockIdx.x * blockDim.x + threadIdx.x; // MALL*128 float4
    size_t row = i >> 7;
    int c = (int)(i & 127);
    int tok = seqs[row];
    float4 v = ((const float4*)(emb + (size_t)tok * DD))[c];
    __nv_bfloat16 h0 = __float2bfloat16_rn(v.x), h1 = __float2bfloat16_rn(v.y);
    __nv_bfloat16 h2 = __float2bfloat16_rn(v.z), h3 = __float2bfloat16_rn(v.w);
    uint2 hv, lv;
    hv.x = bfu(h0) | (bfu(h1) << 16); hv.y = bfu(h2) | (bfu(h3) << 16);
    lv.x = bfu(__float2bfloat16_rn(v.x - __bfloat162float(h0))) |
           (bfu(__float2bfloat16_rn(v.y - __bfloat162float(h1))) << 16);
    lv.y = bfu(__float2bfloat16_rn(v.z - __bfloat162float(h2))) |
           (bfu(__float2bfloat16_rn(v.w - __bfloat162float(h3))) << 16);
    ((uint2*)h)[i] = hv; ((uint2*)l)[i] = lv;
}
__global__ void copy4_kernel(float* __restrict__ dst, const float* __restrict__ src, int n4) {
    int i = blockIdx.x * blockDim.x + threadIdx.x;
    if (i < n4) ((float4*)dst)[i] = ((const float4*)src)[i];
}
__global__ void softmax_kernel(float* __restrict__ P, __nv_bfloat16* __restrict__ ph,
                               __nv_bfloat16* __restrict__ pl) {
    __shared__ float red[256];
    size_t row = blockIdx.x;
    float* p = P + row * NSE;
    int tid = threadIdx.x;
    float v0 = p[tid], v1 = p[tid + 256];
    red[tid] = fmaxf(v0, v1); __syncthreads();
    #pragma unroll
    for (int s = 128; s > 0; s >>= 1) { if (tid < s) red[tid] = fmaxf(red[tid], red[tid + s]); __syncthreads(); }
    float mx = red[0]; __syncthreads();
    float e0 = __expf(v0 - mx), e1 = __expf(v1 - mx);
    red[tid] = e0 + e1; __syncthreads();
    #pragma unroll
    for (int s = 128; s > 0; s >>= 1) { if (tid < s) red[tid] += red[tid + s]; __syncthreads(); }
    float inv = 1.0f / red[0];
    float o0 = e0 * inv, o1 = e1 * inv;
    p[tid] = o0; p[tid + 256] = o1;
    __nv_bfloat16 b0 = __float2bfloat16_rn(o0), b1 = __float2bfloat16_rn(o1);
    ph[row * NSE + tid] = b0;
    ph[row * NSE + tid + 256] = b1;
    pl[row * NSE + tid] = __float2bfloat16_rn(o0 - __bfloat162float(b0));
    pl[row * NSE + tid + 256] = __float2bfloat16_rn(o1 - __bfloat162float(b1));
}
__global__ void split4_kernel(const float* __restrict__ s, __nv_bfloat16* __restrict__ h,
                              __nv_bfloat16* __restrict__ l, int n4) {
    int i = blockIdx.x * 256 + threadIdx.x;
    if (i >= n4) return;
    float4 v = ((const float4*)s)[i];
    __nv_bfloat16 h0 = __float2bfloat16_rn(v.x), h1 = __float2bfloat16_rn(v.y);
    __nv_bfloat16 h2 = __float2bfloat16_rn(v.z), h3 = __float2bfloat16_rn(v.w);
    uint2 hv, lv;
    hv.x = bfu(h0) | (bfu(h1) << 16); hv.y = bfu(h2) | (bfu(h3) << 16);
    lv.x = bfu(__float2bfloat16_rn(v.x - __bfloat162float(h0))) |
           (bfu(__float2bfloat16_rn(v.y - __bfloat162float(h1))) << 16);
    lv.y = bfu(__float2bfloat16_rn(v.z - __bfloat162float(h2))) |
           (bfu(__float2bfloat16_rn(v.w - __bfloat162float(h3))) << 16);
    ((uint2*)h)[i] = hv; ((uint2*)l)[i] = lv;
}
__global__ void splitpad_kernel(const float* __restrict__ s, __nv_bfloat16* __restrict__ h,
                                __nv_bfloat16* __restrict__ l) {
    int i = blockIdx.x * 256 + threadIdx.x;
    if (i >= 128 * DD) return;
    int r = i / DD, c = i % DD;
    float v = (r < NV) ? s[r * DD + c] : 0.0f;
    __nv_bfloat16 hb = __float2bfloat16_rn(v);
    h[i] = hb;
    l[i] = __float2bfloat16_rn(v - __bfloat162float(hb));
}
__global__ void transpose_split_kernel(const float* __restrict__ enc,
                                       __nv_bfloat16* __restrict__ th, __nv_bfloat16* __restrict__ tl) {
    __shared__ float tile[32][33];
    int b = blockIdx.z;
    int d0 = blockIdx.x * 32, s0 = blockIdx.y * 32;
    int x = threadIdx.x, y = threadIdx.y;
    #pragma unroll
    for (int i = 0; i < 32; i += 8)
        tile[y + i][x] = enc[((size_t)b * NSE + s0 + y + i) * DD + d0 + x];
    __syncthreads();
    #pragma unroll
    for (int i = 0; i < 32; i += 8) {
        float v = tile[x][y + i];
        __nv_bfloat16 hb = __float2bfloat16_rn(v);
        size_t o = ((size_t)b * DD + d0 + y + i) * NSE + s0 + x;
        th[o] = hb;
        tl[o] = __float2bfloat16_rn(v - __bfloat162float(hb));
    }
}

// ---------------- mma.sync split-bf16 NT GEMM, 4-stage pipeline ----------------
// epi: 0 f32, 2 f32*mask(+bias), 3 xp transposed (staged, coalesced), 4 bf16-split, 5 tanh*mask bf16-split
#define LDT 40
#define TILE_B (128 * LDT * 2)       // 10240
#define STAGE_B (4 * TILE_B)         // 40960
#define GM_SMEM (4 * STAGE_B)        // 163840
__global__ void __launch_bounds__(256, 1) gemm_mma(
    const __nv_bfloat16* __restrict__ A0h, const __nv_bfloat16* __restrict__ A0l,
    const __nv_bfloat16* __restrict__ A1h, const __nv_bfloat16* __restrict__ A1l,
    int K0, int K1, int K,
    const __nv_bfloat16* __restrict__ Wh, const __nv_bfloat16* __restrict__ Wl, int nvalid,
    float* __restrict__ C, __nv_bfloat16* __restrict__ Obh, __nv_bfloat16* __restrict__ Obl, int ldc,
    size_t sA, size_t sW, size_t sC,
    float scale, const float* __restrict__ bias, const float* __restrict__ mask, int epi)
{
    uint32_t smb = smem_u32(smf);
    int tid = threadIdx.x, lane = tid & 31, wid = tid >> 5;
    int wm = wid >> 2, wn = wid & 3;
    int bz = blockIdx.z;
    int nBase = blockIdx.x * 128, mBase = blockIdx.y * 128;
    const __nv_bfloat16* a0h = A0h + (size_t)bz * sA;
    const __nv_bfloat16* a0l = A0l + (size_t)bz * sA;
    const __nv_bfloat16* wh  = Wh  + (size_t)bz * sW;
    const __nv_bfloat16* wl  = Wl  + (size_t)bz * sW;
    float* Cb = C + (size_t)bz * sC;
    __nv_bfloat16* obh = Obh + (size_t)bz * sC;   // FIX: batch offset for bf16 outputs
    __nv_bfloat16* obl = Obl + (size_t)bz * sC;

    float acc[4][4][4];
    #pragma unroll
    for (int i = 0; i < 4; i++)
        #pragma unroll
        for (int j = 0; j < 4; j++)
            #pragma unroll
            for (int q = 0; q < 4; q++) acc[i][j][q] = 0.0f;

    auto load_chunk = [&](int buf, int c) {
        int kOff = c * 32;
        const __nv_bfloat16 *ah, *al;
        int lda, ka;
        if (kOff < K0) { ah = a0h; al = a0l; lda = K0; ka = kOff; }
        else           { ah = A1h; al = A1l; lda = K1; ka = kOff - K0; }
        uint32_t sb = smb + buf * STAGE_B;
        #pragma unroll
        for (int p = 0; p < 8; p++) {
            int idx = p * 256 + tid;
            int tile = idx >> 9, rem = idx & 511;
            int r = rem >> 2, c16 = rem & 3;
            uint32_t dst = sb + tile * TILE_B + r * (LDT * 2) + c16 * 16;
            if (tile == 0)      cpasync16(dst, ah + (size_t)(mBase + r) * lda + ka + c16 * 8, 16);
            else if (tile == 1) cpasync16(dst, al + (size_t)(mBase + r) * lda + ka + c16 * 8, 16);
            else if (tile == 2) cpasync16(dst, wh + (size_t)(nBase + r) * K + kOff + c16 * 8, (nBase + r < nvalid) ? 16 : 0);
            else                cpasync16(dst, wl + (size_t)(nBase + r) * K + kOff + c16 * 8, (nBase + r < nvalid) ? 16 : 0);
        }
    };

    int aRow = lane & 15, aK = (lane >> 4) * 8;
    int bRow = (lane & 7) + ((lane >> 4) & 1) * 8, bK = ((lane >> 3) & 1) * 8;

    int nk = K / 32;
    #pragma unroll
    for (int s = 0; s < 3; s++) {
        if (s < nk) load_chunk(s, s);
        CP_COMMIT();
    }
    for (int c = 0; c < nk; c++) {
        CP_WAIT2();
        __syncthreads();
        if (c + 3 < nk) load_chunk((c + 3) & 3, c + 3);
        CP_COMMIT();
        uint32_t sb = smb + (c & 3) * STAGE_B;
        #pragma unroll
        for (int ks = 0; ks < 2; ks++) {
            uint32_t ahf[4][4], alf[4][4], bhf[4][2], blf[4][2];
            #pragma unroll
            for (int mf = 0; mf < 4; mf++) {
                uint32_t ra = sb + ((wm * 64 + mf * 16 + aRow) * LDT + ks * 16 + aK) * 2;
                ldsm_x4(ahf[mf], ra);
                ldsm_x4(alf[mf], ra + TILE_B);
            }
            #pragma unroll
            for (int np = 0; np < 2; np++) {
                uint32_t rb = sb + 2 * TILE_B + ((wn * 32 + np * 16 + bRow) * LDT + ks * 16 + bK) * 2;
                uint32_t tmp[4];
                ldsm_x4(tmp, rb);
                bhf[np * 2][0] = tmp[0]; bhf[np * 2][1] = tmp[1];
                bhf[np * 2 + 1][0] = tmp[2]; bhf[np * 2 + 1][1] = tmp[3];
                ldsm_x4(tmp, rb + TILE_B);
                blf[np * 2][0] = tmp[0]; blf[np * 2][1] = tmp[1];
                blf[np * 2 + 1][0] = tmp[2]; blf[np * 2 + 1][1] = tmp[3];
            }
            #pragma unroll
            for (int mf = 0; mf < 4; mf++)
                #pragma unroll
                for (int nf = 0; nf < 4; nf++) {
                    mma16816(acc[mf][nf], ahf[mf], bhf[nf]);
                    mma16816(acc[mf][nf], ahf[mf], blf[nf]);
                    mma16816(acc[mf][nf], alf[mf], bhf[nf]);
                }
        }
    }

    int rOff = lane >> 2, cOff = (lane & 3) * 2;

    if (epi == 3) {
        // staged transpose store: smem col-major [col][132], then coalesced rows of t
        __syncthreads();
        #pragma unroll
        for (int mf = 0; mf < 4; mf++) {
            int ml0 = wm * 64 + mf * 16 + rOff;
            #pragma unroll
            for (int nf = 0; nf < 4; nf++) {
                int cl = wn * 32 + nf * 8 + cOff;
                float b0 = bias[nBase + cl], b1 = bias[nBase + cl + 1];
                smf[cl * 132 + ml0]           = acc[mf][nf][0] * scale + b0;
                smf[(cl + 1) * 132 + ml0]     = acc[mf][nf][1] * scale + b1;
                smf[cl * 132 + ml0 + 8]       = acc[mf][nf][2] * scale + b0;
                smf[(cl + 1) * 132 + ml0 + 8] = acc[mf][nf][3] * scale + b1;
            }
        }
        __syncthreads();
        int mm = mBase >> 9, tt0 = mBase & 511;
        #pragma unroll
        for (int k = 0; k < 16; k++) {
            int idx = k * 256 + tid;
            int j = idx >> 5, c4 = (idx & 31) * 4;
            float4 v = *(float4*)&smf[j * 132 + c4];
            *(float4*)(Cb + ((size_t)mm * D3 + nBase + j) * NS + tt0 + c4) = v;
        }
        return;
    }

    #pragma unroll
    for (int mf = 0; mf < 4; mf++) {
        int mrow0 = mBase + wm * 64 + mf * 16 + rOff;
        int mrow1 = mrow0 + 8;
        float mk0 = 1.0f, mk1 = 1.0f;
        if (epi == 2 || epi == 5) {
            mk0 = mask[(size_t)bz * (sC / ldc) + mrow0];
            mk1 = mask[(size_t)bz * (sC / ldc) + mrow1];
        }
        #pragma unroll
        for (int nf = 0; nf < 4; nf++) {
            int col = nBase + wn * 32 + nf * 8 + cOff;
            if (col >= nvalid) continue;
            float v0 = acc[mf][nf][0] * scale, v1 = acc[mf][nf][1] * scale;
            float v2 = acc[mf][nf][2] * scale, v3 = acc[mf][nf][3] * scale;
            if (bias) {
                float b0 = bias[col], b1 = bias[col + 1];
                v0 += b0; v1 += b1; v2 += b0; v3 += b1;
            }
            if (epi == 0) {
                *(float2*)(Cb + (size_t)mrow0 * ldc + col) = make_float2(v0, v1);
                *(float2*)(Cb + (size_t)mrow1 * ldc + col) = make_float2(v2, v3);
            } else if (epi == 2) {
                v0 *= mk0; v1 *= mk0; v2 *= mk1; v3 *= mk1;
                *(float2*)(Cb + (size_t)mrow0 * ldc + col) = make_float2(v0, v1);
                *(float2*)(Cb + (size_t)mrow1 * ldc + col) = make_float2(v2, v3);
            } else {
                if (epi == 5) {
                    v0 = tanh_fast(v0) * mk0; v1 = tanh_fast(v1) * mk0;
                    v2 = tanh_fast(v2) * mk1; v3 = tanh_fast(v3) * mk1;
                }
                __nv_bfloat16 h0 = __float2bfloat16_rn(v0), h1 = __float2bfloat16_rn(v1);
                __nv_bfloat16 h2 = __float2bfloat16_rn(v2), h3 = __float2bfloat16_rn(v3);
                uint32_t hp0 = bfu(h0) | (bfu(h1) << 16);
                uint32_t hp1 = bfu(h2) | (bfu(h3) << 16);
                uint32_t lp0 = bfu(__float2bfloat16_rn(v0 - __bfloat162float(h0))) |
                               (bfu(__float2bfloat16_rn(v1 - __bfloat162float(h1))) << 16);
                uint32_t lp1 = bfu(__float2bfloat16_rn(v2 - __bfloat162float(h2))) |
                               (bfu(__float2bfloat16_rn(v3 - __bfloat162float(h3))) << 16);
                *(uint32_t*)(obh + (size_t)mrow0 * ldc + col) = hp0;
                *(uint32_t*)(obh + (size_t)mrow1 * ldc + col) = hp1;
                *(uint32_t*)(obl + (size_t)mrow0 * ldc + col) = lp0;
                *(uint32_t*)(obl + (size_t)mrow1 * ldc + col) = lp1;
            }
        }
    }
}

// ---------------- per-m-group barrier ----------------
__device__ __forceinline__ void bar_mb(int mb) {
    __syncthreads();
    if (threadIdx.x == 0) {
        __threadfence();
        unsigned gen = g_gen8[mb];
        unsigned old = atomicAdd(&g_cnt8[mb], 1);
        if (old == 15u) {
            atomicExch(&g_cnt8[mb], 0u);
            __threadfence();
            g_gen8[mb] = gen + 1u;
        } else {
            while (g_gen8[mb] == gen) { }
        }
        __threadfence();
    }
    __syncthreads();
}

// persistent per-layer GRU: 128 blocks (16 j x 8 m), 256 threads. xp transposed [m][3D][t].
// Emits y as split bf16 (yh, yl) and the mask.
#define WS_LD 516
#define HS_LD 516
#define GRU_SMEM ((3*32*WS_LD + 16*HS_LD) * 4)
__global__ void __launch_bounds__(256, 1) gru_layer(
    float* __restrict__ hA, float* __restrict__ hB,
    const float* __restrict__ W, const float* __restrict__ bhh,
    const float* __restrict__ xpT,
    __nv_bfloat16* __restrict__ yh, __nv_bfloat16* __restrict__ yl,
    float* __restrict__ maskp)
{
    float* ws = smf;
    float* hs = smf + 3 * 32 * WS_LD;
    int tid = threadIdx.x;
    int lane = tid & 31, w = tid >> 5;
    int wj = w & 3, mg = w >> 2;
    int j_sub = lane >> 2, m_sub = lane & 3;
    int jb = blockIdx.x & 15, mb = blockIdx.x >> 4;
    int jBase = jb * 32, mBase = mb * 16;
    int j_loc = wj * 8 + j_sub;
    int j = jBase + j_loc;
    int m0_loc = mg * 8 + m_sub * 2;

    for (int idx = tid; idx < 96 * 128; idx += 256) {
        int rr = idx >> 7, c = idx & 127;
        int g = rr >> 5, jr = rr & 31;
        float4 v = *(const float4*)(W + (size_t)(g * DD + jBase + jr) * DD + c * 4);
        *(float4*)&ws[rr * WS_LD + c * 4] = v;
    }
    float brv = bhh[j], bzv = bhh[DD + j], bnv = bhh[2 * DD + j];
    const float* wp0 = &ws[(0 * 32 + j_loc) * WS_LD];
    const float* wp1 = &ws[(1 * 32 + j_loc) * WS_LD];
    const float* wp2 = &ws[(2 * 32 + j_loc) * WS_LD];
    const float* hp0 = &hs[(m0_loc + 0) * HS_LD];
    const float* hp1 = &hs[(m0_loc + 1) * HS_LD];
    int m0g = mBase + m0_loc, m1g = m0g + 1;
    const float* xr0p = xpT + ((size_t)m0g * D3 + j) * NS;
    const float* xr1p = xpT + ((size_t)m1g * D3 + j) * NS;

    for (int t = 0; t < NS; t++) {
        const float* hin  = (t & 1) ? hB : hA;
        float*       hout = (t & 1) ? hA : hB;
        #pragma unroll
        for (int it = 0; it < 8; it++) {
            int idx = it * 256 + tid;
            int r = idx >> 7, c = idx & 127;
            *(float4*)&hs[r * HS_LD + c * 4] =
                *(const float4*)(hin + (size_t)(mBase + r) * DD + c * 4);
        }
        __syncthreads();

        unsigned long long a0r = 0, a0z = 0, a0n = 0, a1r = 0, a1z = 0, a1n = 0;
        #pragma unroll 8
        for (int k = 0; k < DD; k += 4) {
            ulonglong2 w0 = *(const ulonglong2*)(wp0 + k);
            ulonglong2 w1 = *(const ulonglong2*)(wp1 + k);
            ulonglong2 w2 = *(const ulonglong2*)(wp2 + k);
            ulonglong2 h0 = *(const ulonglong2*)(hp0 + k);
            ulonglong2 h1 = *(const ulonglong2*)(hp1 + k);
            a0r = fma2(h0.x, w0.x, a0r); a0r = fma2(h0.y, w0.y, a0r);
            a0z = fma2(h0.x, w1.x, a0z); a0z = fma2(h0.y, w1.y, a0z);
            a0n = fma2(h0.x, w2.x, a0n); a0n = fma2(h0.y, w2.y, a0n);
            a1r = fma2(h1.x, w0.x, a1r); a1r = fma2(h1.y, w0.y, a1r);
            a1z = fma2(h1.x, w1.x, a1z); a1z = fma2(h1.y, w1.y, a1z);
            a1n = fma2(h1.x, w2.x, a1n); a1n = fma2(h1.y, w2.y, a1n);
        }
        #pragma unroll
        for (int rsub = 0; rsub < 2; rsub++) {
            float2 pr = unpack2(rsub ? a1r : a0r);
            float2 pz = unpack2(rsub ? a1z : a0z);
            float2 pn = unpack2(rsub ? a1n : a0n);
            float gr = pr.x + pr.y, gz = pz.x + pz.y, gn = pn.x + pn.y;
            int m = rsub ? m1g : m0g;
            const float* xq = rsub ? xr1p : xr0p;
            float xr = xq[t], xz = xq[(size_t)DD * NS + t], xn = xq[(size_t)2 * DD * NS + t];
            float r = sigmoid_fast(xr + gr + brv);
            float z = sigmoid_fast(xz + gz + bzv);
            float n = tanh_fast(xn + r * (gn + bnv));
            float hprev = hs[(m0_loc + rsub) * HS_LD + j];
            float h2 = (1.0f - z) * n + z * hprev;
            hout[(size_t)m * DD + j] = h2;
            size_t yi = ((size_t)m * NS + t) * DD + j;
            __nv_bfloat16 hb = __float2bfloat16_rn(h2);
            yh[yi] = hb;
            yl[yi] = __float2bfloat16_rn(h2 - __bfloat162float(hb));
            if (j == 0) maskp[(size_t)m * NS + t] = (h2 != 0.0f) ? 1.0f : 0.0f;
        }
        bar_mb(mb);
    }
}

extern "C" void kernel_launch(void* const* d_in, const int* in_sizes, int n_in,
                              void* d_out, int out_size) {
    const int*   seqs  = (const int*)d_in[0];
    const float* enc   = (const float*)d_in[2];
    const float* h0    = (const float*)d_in[3];
    const float* emb   = (const float*)d_in[4];
    const float* w_ih  = (const float*)d_in[5];
    const float* w_hh  = (const float*)d_in[6];
    const float* b_ih  = (const float*)d_in[7];
    const float* b_hh  = (const float*)d_in[8];
    const float* attnw = (const float*)d_in[9];
    const float* attnb = (const float*)d_in[10];
    const float* outw  = (const float*)d_in[11];
    const float* outb  = (const float*)d_in[12];
    float* out = (float*)d_out;

    float *xp, *hA, *hB, *mask;
    __nv_bfloat16 *Ah, *Al, *Ph, *Pl, *Ch, *Cl, *Dh, *Dl;
    __nv_bfloat16 *ench, *encl, *encTh, *encTl, *wihh, *wihl, *awh, *awl, *owh, *owl;
    cudaGetSymbolAddress((void**)&xp,   g_xp);
    cudaGetSymbolAddress((void**)&hA,   g_hA);
    cudaGetSymbolAddress((void**)&hB,   g_hB);
    cudaGetSymbolAddress((void**)&mask, g_mask);
    cudaGetSymbolAddress((void**)&Ah, g_Ah);   cudaGetSymbolAddress((void**)&Al, g_Al);
    cudaGetSymbolAddress((void**)&Ph, g_Ph);   cudaGetSymbolAddress((void**)&Pl, g_Pl);
    cudaGetSymbolAddress((void**)&Ch, g_Ch);   cudaGetSymbolAddress((void**)&Cl, g_Cl);
    cudaGetSymbolAddress((void**)&Dh, g_Dh);   cudaGetSymbolAddress((void**)&Dl, g_Dl);
    cudaGetSymbolAddress((void**)&ench, g_ench);   cudaGetSymbolAddress((void**)&encl, g_encl);
    cudaGetSymbolAddress((void**)&encTh, g_encTh); cudaGetSymbolAddress((void**)&encTl, g_encTl);
    cudaGetSymbolAddress((void**)&wihh, g_wihh);   cudaGetSymbolAddress((void**)&wihl, g_wihl);
    cudaGetSymbolAddress((void**)&awh, g_awh);     cudaGetSymbolAddress((void**)&awl, g_awl);
    cudaGetSymbolAddress((void**)&owh, g_owh);     cudaGetSymbolAddress((void**)&owl, g_owl);

    static int attr_set = 0;
    if (!attr_set) {
        cudaFuncSetAttribute(gru_layer, cudaFuncAttributeMaxDynamicSharedMemorySize, GRU_SMEM);
        cudaFuncSetAttribute(gemm_mma, cudaFuncAttributeMaxDynamicSharedMemorySize, GM_SMEM);
        attr_set = 1;
    }

    const size_t OUT_H    = (size_t)MALL * NV;
    const size_t OUT_ATTN = OUT_H + (size_t)NL * NB * DD;
    float* attnP = out + OUT_ATTN;
    const float SC = 0.044194173824159216f;

    split4_kernel<<<(NL * D3 * DD / 4 + 255) / 256, 256>>>(w_ih, wihh, wihl, NL * D3 * DD / 4);
    split4_kernel<<<(DD * 2 * DD / 4 + 255) / 256, 256>>>(attnw, awh, awl, DD * 2 * DD / 4);
    splitpad_kernel<<<(128 * DD + 255) / 256, 256>>>(outw, owh, owl);
    split4_kernel<<<(NB * NSE * DD / 4 + 255) / 256, 256>>>(enc, ench, encl, NB * NSE * DD / 4);
    transpose_split_kernel<<<dim3(16, 16, 128), dim3(32, 8)>>>(enc, encTh, encTl);

    embed_split_kernel<<<(MALL * (DD / 4)) / 256, 256>>>(seqs, emb, Ah, Al);

    for (int l = 0; l < NL; l++) {
        gemm_mma<<<dim3(12, 512, 1), 256, GM_SMEM>>>(
            Ah, Al, nullptr, nullptr, DD, DD, DD,
            wihh + (size_t)l * D3 * DD, wihl + (size_t)l * D3 * DD, D3,
            xp, nullptr, nullptr, 0, 0, 0, 0, 1.0f, b_ih + (size_t)l * D3, nullptr, 3);
        copy4_kernel<<<64, 256>>>(hA, h0 + (size_t)l * NB * DD, NB * DD / 4);
        gru_layer<<<128, 256, GRU_SMEM>>>(
            hA, hB, w_hh + (size_t)l * D3 * DD, b_hh + (size_t)l * D3, xp, Ah, Al, mask);
        copy4_kernel<<<64, 256>>>(out + OUT_H + (size_t)l * NB * DD, hA, NB * DD / 4);
    }

    // scores -> attnP (f32, output region)
    gemm_mma<<<dim3(4, 4, 128), 256, GM_SMEM>>>(
        Ah, Al, nullptr, nullptr, DD, DD, DD,
        ench, encl, NSE,
        attnP, nullptr, nullptr, NSE, (size_t)NS * DD, (size_t)NSE * DD, (size_t)NS * NSE,
        SC, nullptr, nullptr, 0);
    softmax_kernel<<<MALL, 256>>>(attnP, Ph, Pl);

    // context (bf16 split out)
    gemm_mma<<<dim3(4, 4, 128), 256, GM_SMEM>>>(
        Ph, Pl, nullptr, nullptr, NSE, NSE, NSE,
        encTh, encTl, DD,
        nullptr, Ch, Cl, DD, (size_t)NS * NSE, (size_t)DD * NSE, (size_t)NS * DD,
        1.0f, nullptr, nullptr, 4);

    // attn_masked = tanh([dec|ctx] @ attn_w^T + attn_b)*mask (bf16 split out)
    gemm_mma<<<dim3(4, 512, 1), 256, GM_SMEM>>>(
        Ah, Al, Ch, Cl, DD, DD, 2 * DD,
        awh, awl, DD,
        nullptr, Dh, Dl, DD, 0, 0, 0, 1.0f, attnb, mask, 5);

    // logits
    gemm_mma<<<dim3(1, 512, 1), 256, GM_SMEM>>>(
        Dh, Dl, nullptr, nullptr, DD, DD, DD,
        owh, owl, NV,
        out, nullptr, nullptr, NV, 0, 0, 0, 1.0f, outb, mask, 2);
}

// round 11
// speedup vs baseline: 1.3467x; 1.0514x over previous
#include <cuda_runtime.h>
#include <cuda_bf16.h>
#include <math.h>
#include <stdint.h>

#define NL 3
#define DD 512
#define NV 100
#define NB 128
#define NS 512
#define NSE 512
#define MALL (NB*NS)
#define D3 (3*DD)

// ---------------- scratch ----------------
__device__ float g_xp[(size_t)MALL * D3];     // xp plain [b*NS+t][3D]
__device__ float g_G[NB * D3];                // per-step gate preactivations
__device__ float g_h[NB * DD];                // fp32 recurrent state
__device__ float g_mask[MALL];
__device__ unsigned g_cnt4[4];
__device__ volatile unsigned g_gen4[4];
// bf16 split buffers
__device__ __nv_bfloat16 g_hsh[NB * DD];      // h state bf16 split
__device__ __nv_bfloat16 g_hsl[NB * DD];
__device__ __nv_bfloat16 g_Ah[(size_t)MALL * DD];   // x / y / dec
__device__ __nv_bfloat16 g_Al[(size_t)MALL * DD];
__device__ __nv_bfloat16 g_Ph[(size_t)MALL * NSE];  // softmax probs
__device__ __nv_bfloat16 g_Pl[(size_t)MALL * NSE];
__device__ __nv_bfloat16 g_Ch[(size_t)MALL * DD];   // context
__device__ __nv_bfloat16 g_Cl[(size_t)MALL * DD];
__device__ __nv_bfloat16 g_Dh[(size_t)MALL * DD];   // attn_masked
__device__ __nv_bfloat16 g_Dl[(size_t)MALL * DD];
__device__ __nv_bfloat16 g_ench[(size_t)NB * NSE * DD];
__device__ __nv_bfloat16 g_encl[(size_t)NB * NSE * DD];
__device__ __nv_bfloat16 g_encTh[(size_t)NB * DD * NSE];
__device__ __nv_bfloat16 g_encTl[(size_t)NB * DD * NSE];
__device__ __nv_bfloat16 g_wihh[(size_t)NL * D3 * DD];
__device__ __nv_bfloat16 g_wihl[(size_t)NL * D3 * DD];
__device__ __nv_bfloat16 g_whhh[(size_t)NL * D3 * DD];
__device__ __nv_bfloat16 g_whhl[(size_t)NL * D3 * DD];
__device__ __nv_bfloat16 g_awh[(size_t)DD * 2 * DD];
__device__ __nv_bfloat16 g_awl[(size_t)DD * 2 * DD];
__device__ __nv_bfloat16 g_owh[128 * DD];
__device__ __nv_bfloat16 g_owl[128 * DD];

extern __shared__ float smf[];

// ---------------- helpers ----------------
__device__ __forceinline__ float tanh_fast(float x) {
    float y;
    asm("tanh.approx.f32 %0, %1;" : "=f"(y) : "f"(x));
    return y;
}
__device__ __forceinline__ float sigmoid_fast(float x) { return 1.0f / (1.0f + __expf(-x)); }
__device__ __forceinline__ uint32_t smem_u32(const void* p) {
    uint32_t a;
    asm("{ .reg .u64 t; cvta.to.shared.u64 t, %1; cvt.u32.u64 %0, t; }" : "=r"(a) : "l"(p));
    return a;
}
__device__ __forceinline__ unsigned bfu(__nv_bfloat16 b) {
    unsigned short s = __bfloat16_as_ushort(b);
    return (unsigned)s;
}

// ---------------- mma.sync primitives ----------------
__device__ __forceinline__ void mma16816(float* d, const uint32_t* a, const uint32_t* b) {
    asm volatile(
        "mma.sync.aligned.m16n8k16.row.col.f32.bf16.bf16.f32 "
        "{%0,%1,%2,%3}, {%4,%5,%6,%7}, {%8,%9}, {%0,%1,%2,%3};"
        : "+f"(d[0]), "+f"(d[1]), "+f"(d[2]), "+f"(d[3])
        : "r"(a[0]), "r"(a[1]), "r"(a[2]), "r"(a[3]), "r"(b[0]), "r"(b[1]));
}
__device__ __forceinline__ void ldsm_x4(uint32_t* r, uint32_t addr) {
    asm volatile("ldmatrix.sync.aligned.m8n8.x4.shared.b16 {%0,%1,%2,%3}, [%4];"
        : "=r"(r[0]), "=r"(r[1]), "=r"(r[2]), "=r"(r[3]) : "r"(addr));
}
__device__ __forceinline__ void cpasync16(uint32_t dst, const void* src, int sz) {
    asm volatile("cp.async.ca.shared.global [%0], [%1], 16, %2;" :: "r"(dst), "l"(src), "r"(sz) : "memory");
}
#define CP_COMMIT() asm volatile("cp.async.commit_group;" ::: "memory")
#define CP_WAIT2()  asm volatile("cp.async.wait_group 2;" ::: "memory")

// ---------------- small kernels ----------------
__global__ void embed_split_kernel(const int* __restrict__ seqs, const float* __restrict__ emb,
                                   __nv_bfloat16* __restrict__ h, __nv_bfloat16* __restrict__ l) {
    size_t i = (size_t)blockIdx.x * blockDim.x + threadIdx.x;
    size_t row = i >> 7;
    int c = (int)(i & 127);
    int tok = seqs[row];
    float4 v = ((const float4*)(emb + (size_t)tok * DD))[c];
    __nv_bfloat16 h0 = __float2bfloat16_rn(v.x), h1 = __float2bfloat16_rn(v.y);
    __nv_bfloat16 h2 = __float2bfloat16_rn(v.z), h3 = __float2bfloat16_rn(v.w);
    uint2 hv, lv;
    hv.x = bfu(h0) | (bfu(h1) << 16); hv.y = bfu(h2) | (bfu(h3) << 16);
    lv.x = bfu(__float2bfloat16_rn(v.x - __bfloat162float(h0))) |
           (bfu(__float2bfloat16_rn(v.y - __bfloat162float(h1))) << 16);
    lv.y = bfu(__float2bfloat16_rn(v.z - __bfloat162float(h2))) |
           (bfu(__float2bfloat16_rn(v.w - __bfloat162float(h3))) << 16);
    ((uint2*)h)[i] = hv; ((uint2*)l)[i] = lv;
}
__global__ void copy4_kernel(float* __restrict__ dst, const float* __restrict__ src, int n4) {
    int i = blockIdx.x * blockDim.x + threadIdx.x;
    if (i < n4) ((float4*)dst)[i] = ((const float4*)src)[i];
}
__global__ void h_init_kernel(const float* __restrict__ h0, float* __restrict__ hstate,
                              __nv_bfloat16* __restrict__ hh, __nv_bfloat16* __restrict__ hl) {
    int i = blockIdx.x * 256 + threadIdx.x;   // over NB*DD/4
    if (i >= NB * DD / 4) return;
    float4 v = ((const float4*)h0)[i];
    ((float4*)hstate)[i] = v;
    __nv_bfloat16 a0 = __float2bfloat16_rn(v.x), a1 = __float2bfloat16_rn(v.y);
    __nv_bfloat16 a2 = __float2bfloat16_rn(v.z), a3 = __float2bfloat16_rn(v.w);
    uint2 hv, lv;
    hv.x = bfu(a0) | (bfu(a1) << 16); hv.y = bfu(a2) | (bfu(a3) << 16);
    lv.x = bfu(__float2bfloat16_rn(v.x - __bfloat162float(a0))) |
           (bfu(__float2bfloat16_rn(v.y - __bfloat162float(a1))) << 16);
    lv.y = bfu(__float2bfloat16_rn(v.z - __bfloat162float(a2))) |
           (bfu(__float2bfloat16_rn(v.w - __bfloat162float(a3))) << 16);
    ((uint2*)hh)[i] = hv; ((uint2*)hl)[i] = lv;
}
__global__ void softmax_kernel(float* __restrict__ P, __nv_bfloat16* __restrict__ ph,
                               __nv_bfloat16* __restrict__ pl) {
    __shared__ float red[256];
    size_t row = blockIdx.x;
    float* p = P + row * NSE;
    int tid = threadIdx.x;
    float v0 = p[tid], v1 = p[tid + 256];
    red[tid] = fmaxf(v0, v1); __syncthreads();
    #pragma unroll
    for (int s = 128; s > 0; s >>= 1) { if (tid < s) red[tid] = fmaxf(red[tid], red[tid + s]); __syncthreads(); }
    float mx = red[0]; __syncthreads();
    float e0 = __expf(v0 - mx), e1 = __expf(v1 - mx);
    red[tid] = e0 + e1; __syncthreads();
    #pragma unroll
    for (int s = 128; s > 0; s >>= 1) { if (tid < s) red[tid] += red[tid + s]; __syncthreads(); }
    float inv = 1.0f / red[0];
    float o0 = e0 * inv, o1 = e1 * inv;
    p[tid] = o0; p[tid + 256] = o1;
    __nv_bfloat16 b0 = __float2bfloat16_rn(o0), b1 = __float2bfloat16_rn(o1);
    ph[row * NSE + tid] = b0;
    ph[row * NSE + tid + 256] = b1;
    pl[row * NSE + tid] = __float2bfloat16_rn(o0 - __bfloat162float(b0));
    pl[row * NSE + tid + 256] = __float2bfloat16_rn(o1 - __bfloat162float(b1));
}
__global__ void split4_kernel(const float* __restrict__ s, __nv_bfloat16* __restrict__ h,
                              __nv_bfloat16* __restrict__ l, int n4) {
    int i = blockIdx.x * 256 + threadIdx.x;
    if (i >= n4) return;
    float4 v = ((const float4*)s)[i];
    __nv_bfloat16 h0 = __float2bfloat16_rn(v.x), h1 = __float2bfloat16_rn(v.y);
    __nv_bfloat16 h2 = __float2bfloat16_rn(v.z), h3 = __float2bfloat16_rn(v.w);
    uint2 hv, lv;
    hv.x = bfu(h0) | (bfu(h1) << 16); hv.y = bfu(h2) | (bfu(h3) << 16);
    lv.x = bfu(__float2bfloat16_rn(v.x - __bfloat162float(h0))) |
           (bfu(__float2bfloat16_rn(v.y - __bfloat162float(h1))) << 16);
    lv.y = bfu(__float2bfloat16_rn(v.z - __bfloat162float(h2))) |
           (bfu(__float2bfloat16_rn(v.w - __bfloat162float(h3))) << 16);
    ((uint2*)h)[i] = hv; ((uint2*)l)[i] = lv;
}
__global__ void splitpad_kernel(const float* __restrict__ s, __nv_bfloat16* __restrict__ h,
                                __nv_bfloat16* __restrict__ l) {
    int i = blockIdx.x * 256 + threadIdx.x;
    if (i >= 128 * DD) return;
    int r = i / DD, c = i % DD;
    float v = (r < NV) ? s[r * DD + c] : 0.0f;
    __nv_bfloat16 hb = __float2bfloat16_rn(v);
    h[i] = hb;
    l[i] = __float2bfloat16_rn(v - __bfloat162float(hb));
}
__global__ void transpose_split_kernel(const float* __restrict__ enc,
                                       __nv_bfloat16* __restrict__ th, __nv_bfloat16* __restrict__ tl) {
    __shared__ float tile[32][33];
    int b = blockIdx.z;
    int d0 = blockIdx.x * 32, s0 = blockIdx.y * 32;
    int x = threadIdx.x, y = threadIdx.y;
    #pragma unroll
    for (int i = 0; i < 32; i += 8)
        tile[y + i][x] = enc[((size_t)b * NSE + s0 + y + i) * DD + d0 + x];
    __syncthreads();
    #pragma unroll
    for (int i = 0; i < 32; i += 8) {
        float v = tile[x][y + i];
        __nv_bfloat16 hb = __float2bfloat16_rn(v);
        size_t o = ((size_t)b * DD + d0 + y + i) * NSE + s0 + x;
        th[o] = hb;
        tl[o] = __float2bfloat16_rn(v - __bfloat162float(hb));
    }
}

// ---------------- mma.sync split-bf16 NT GEMM, 4-stage pipeline ----------------
// epi: 0 f32(+bias), 2 f32*mask(+bias), 4 bf16-split, 5 tanh*mask bf16-split
#define LDT 40
#define TILE_B (128 * LDT * 2)
#define STAGE_B (4 * TILE_B)
#define GM_SMEM (4 * STAGE_B)        // 163840
__global__ void __launch_bounds__(256, 1) gemm_mma(
    const __nv_bfloat16* __restrict__ A0h, const __nv_bfloat16* __restrict__ A0l,
    const __nv_bfloat16* __restrict__ A1h, const __nv_bfloat16* __restrict__ A1l,
    int K0, int K1, int K,
    const __nv_bfloat16* __restrict__ Wh, const __nv_bfloat16* __restrict__ Wl, int nvalid,
    float* __restrict__ C, __nv_bfloat16* __restrict__ Obh, __nv_bfloat16* __restrict__ Obl, int ldc,
    size_t sA, size_t sW, size_t sC,
    float scale, const float* __restrict__ bias, const float* __restrict__ mask, int epi)
{
    uint32_t smb = smem_u32(smf);
    int tid = threadIdx.x, lane = tid & 31, wid = tid >> 5;
    int wm = wid >> 2, wn = wid & 3;
    int bz = blockIdx.z;
    int nBase = blockIdx.x * 128, mBase = blockIdx.y * 128;
    const __nv_bfloat16* a0h = A0h + (size_t)bz * sA;
    const __nv_bfloat16* a0l = A0l + (size_t)bz * sA;
    const __nv_bfloat16* wh  = Wh  + (size_t)bz * sW;
    const __nv_bfloat16* wl  = Wl  + (size_t)bz * sW;
    float* Cb = C + (size_t)bz * sC;
    __nv_bfloat16* obh = Obh + (size_t)bz * sC;
    __nv_bfloat16* obl = Obl + (size_t)bz * sC;

    float acc[4][4][4];
    #pragma unroll
    for (int i = 0; i < 4; i++)
        #pragma unroll
        for (int j = 0; j < 4; j++)
            #pragma unroll
            for (int q = 0; q < 4; q++) acc[i][j][q] = 0.0f;

    auto load_chunk = [&](int buf, int c) {
        int kOff = c * 32;
        const __nv_bfloat16 *ah, *al;
        int lda, ka;
        if (kOff < K0) { ah = a0h; al = a0l; lda = K0; ka = kOff; }
        else           { ah = A1h; al = A1l; lda = K1; ka = kOff - K0; }
        uint32_t sb = smb + buf * STAGE_B;
        #pragma unroll
        for (int p = 0; p < 8; p++) {
            int idx = p * 256 + tid;
            int tile = idx >> 9, rem = idx & 511;
            int r = rem >> 2, c16 = rem & 3;
            uint32_t dst = sb + tile * TILE_B + r * (LDT * 2) + c16 * 16;
            if (tile == 0)      cpasync16(dst, ah + (size_t)(mBase + r) * lda + ka + c16 * 8, 16);
            else if (tile == 1) cpasync16(dst, al + (size_t)(mBase + r) * lda + ka + c16 * 8, 16);
            else if (tile == 2) cpasync16(dst, wh + (size_t)(nBase + r) * K + kOff + c16 * 8, (nBase + r < nvalid) ? 16 : 0);
            else                cpasync16(dst, wl + (size_t)(nBase + r) * K + kOff + c16 * 8, (nBase + r < nvalid) ? 16 : 0);
        }
    };

    int aRow = lane & 15, aK = (lane >> 4) * 8;
    int bRow = (lane & 7) + ((lane >> 4) & 1) * 8, bK = ((lane >> 3) & 1) * 8;

    int nk = K / 32;
    #pragma unroll
    for (int s = 0; s < 3; s++) {
        if (s < nk) load_chunk(s, s);
        CP_COMMIT();
    }
    for (int c = 0; c < nk; c++) {
        CP_WAIT2();
        __syncthreads();
        if (c + 3 < nk) load_chunk((c + 3) & 3, c + 3);
        CP_COMMIT();
        uint32_t sb = smb + (c & 3) * STAGE_B;
        #pragma unroll
        for (int ks = 0; ks < 2; ks++) {
            uint32_t ahf[4][4], alf[4][4], bhf[4][2], blf[4][2];
            #pragma unroll
            for (int mf = 0; mf < 4; mf++) {
                uint32_t ra = sb + ((wm * 64 + mf * 16 + aRow) * LDT + ks * 16 + aK) * 2;
                ldsm_x4(ahf[mf], ra);
                ldsm_x4(alf[mf], ra + TILE_B);
            }
            #pragma unroll
            for (int np = 0; np < 2; np++) {
                uint32_t rb = sb + 2 * TILE_B + ((wn * 32 + np * 16 + bRow) * LDT + ks * 16 + bK) * 2;
                uint32_t tmp[4];
                ldsm_x4(tmp, rb);
                bhf[np * 2][0] = tmp[0]; bhf[np * 2][1] = tmp[1];
                bhf[np * 2 + 1][0] = tmp[2]; bhf[np * 2 + 1][1] = tmp[3];
                ldsm_x4(tmp, rb + TILE_B);
                blf[np * 2][0] = tmp[0]; blf[np * 2][1] = tmp[1];
                blf[np * 2 + 1][0] = tmp[2]; blf[np * 2 + 1][1] = tmp[3];
            }
            #pragma unroll
            for (int mf = 0; mf < 4; mf++)
                #pragma unroll
                for (int nf = 0; nf < 4; nf++) {
                    mma16816(acc[mf][nf], ahf[mf], bhf[nf]);
                    mma16816(acc[mf][nf], ahf[mf], blf[nf]);
                    mma16816(acc[mf][nf], alf[mf], bhf[nf]);
                }
        }
    }

    int rOff = lane >> 2, cOff = (lane & 3) * 2;
    #pragma unroll
    for (int mf = 0; mf < 4; mf++) {
        int mrow0 = mBase + wm * 64 + mf * 16 + rOff;
        int mrow1 = mrow0 + 8;
        float mk0 = 1.0f, mk1 = 1.0f;
        if (epi == 2 || epi == 5) {
            mk0 = mask[(size_t)bz * (sC / ldc) + mrow0];
            mk1 = mask[(size_t)bz * (sC / ldc) + mrow1];
        }
        #pragma unroll
        for (int nf = 0; nf < 4; nf++) {
            int col = nBase + wn * 32 + nf * 8 + cOff;
            if (col >= nvalid) continue;
            float v0 = acc[mf][nf][0] * scale, v1 = acc[mf][nf][1] * scale;
            float v2 = acc[mf][nf][2] * scale, v3 = acc[mf][nf][3] * scale;
            if (bias) {
                float b0 = bias[col], b1 = bias[col + 1];
                v0 += b0; v1 += b1; v2 += b0; v3 += b1;
            }
            if (epi == 0) {
                *(float2*)(Cb + (size_t)mrow0 * ldc + col) = make_float2(v0, v1);
                *(float2*)(Cb + (size_t)mrow1 * ldc + col) = make_float2(v2, v3);
            } else if (epi == 2) {
                v0 *= mk0; v1 *= mk0; v2 *= mk1; v3 *= mk1;
                *(float2*)(Cb + (size_t)mrow0 * ldc + col) = make_float2(v0, v1);
                *(float2*)(Cb + (size_t)mrow1 * ldc + col) = make_float2(v2, v3);
            } else {
                if (epi == 5) {
                    v0 = tanh_fast(v0) * mk0; v1 = tanh_fast(v1) * mk0;
                    v2 = tanh_fast(v2) * mk1; v3 = tanh_fast(v3) * mk1;
                }
                __nv_bfloat16 h0 = __float2bfloat16_rn(v0), h1 = __float2bfloat16_rn(v1);
                __nv_bfloat16 h2 = __float2bfloat16_rn(v2), h3 = __float2bfloat16_rn(v3);
                uint32_t hp0 = bfu(h0) | (bfu(h1) << 16);
                uint32_t hp1 = bfu(h2) | (bfu(h3) << 16);
                uint32_t lp0 = bfu(__float2bfloat16_rn(v0 - __bfloat162float(h0))) |
                               (bfu(__float2bfloat16_rn(v1 - __bfloat162float(h1))) << 16);
                uint32_t lp1 = bfu(__float2bfloat16_rn(v2 - __bfloat162float(h2))) |
                               (bfu(__float2bfloat16_rn(v3 - __bfloat162float(h3))) << 16);
                *(uint32_t*)(obh + (size_t)mrow0 * ldc + col) = hp0;
                *(uint32_t*)(obh + (size_t)mrow1 * ldc + col) = hp1;
                *(uint32_t*)(obl + (size_t)mrow0 * ldc + col) = lp0;
                *(uint32_t*)(obl + (size_t)mrow1 * ldc + col) = lp1;
            }
        }
    }
}

// ---------------- per-m-group barrier (32 blocks per group) ----------------
__device__ __forceinline__ void bar4(int grp) {
    __syncthreads();
    if (threadIdx.x == 0) {
        __threadfence();
        unsigned gen = g_gen4[grp];
        unsigned old = atomicAdd(&g_cnt4[grp], 1);
        if (old == 31u) {
            atomicExch(&g_cnt4[grp], 0u);
            __threadfence();
            g_gen4[grp] = gen + 1u;
        } else {
            while (g_gen4[grp] == gen) { }
        }
        __threadfence();
    }
    __syncthreads();
}

// ---------------- persistent tensor-core GRU ----------------
// 128 blocks = 4 m-groups (32 batch rows) x 32 n-tiles (48 W_hh rows). 192 threads (6 warps: 2m x 3n).
#define LDW 520
#define GRUW_B (48 * LDW * 2)        // 49920 bytes per W array
#define GRUH_B (32 * LDW * 2)        // 33280 bytes per h array
#define GRU2_SMEM (2 * GRUW_B + 2 * GRUH_B)   // 166400
__global__ void __launch_bounds__(192, 1) gru_mma(
    const __nv_bfloat16* __restrict__ Wh, const __nv_bfloat16* __restrict__ Wl,
    const float* __restrict__ bhh, const float* __restrict__ xp,
    float* __restrict__ G, float* __restrict__ hstate,
    __nv_bfloat16* __restrict__ hsh, __nv_bfloat16* __restrict__ hsl,
    __nv_bfloat16* __restrict__ yh, __nv_bfloat16* __restrict__ yl,
    float* __restrict__ maskp)
{
    char* sm = (char*)smf;
    uint32_t smb = smem_u32(sm);
    int tid = threadIdx.x, lane = tid & 31, w = tid >> 5;
    int mb = blockIdx.x >> 5, nb = blockIdx.x & 31;
    int warp_m = w & 1, warp_n = w >> 1;   // 2 x 3

    // stage W slice (48 rows x 512) hi/lo once
    for (int idx = tid; idx < 48 * 64; idx += 192) {
        int r = idx >> 6, c = idx & 63;
        *(uint4*)(sm + r * (LDW * 2) + c * 16) =
            *(const uint4*)(Wh + (size_t)(nb * 48 + r) * DD + c * 8);
        *(uint4*)(sm + GRUW_B + r * (LDW * 2) + c * 16) =
            *(const uint4*)(Wl + (size_t)(nb * 48 + r) * DD + c * 8);
    }

    int aRow = lane & 15, aK = (lane >> 4) * 8;
    int bRow = (lane & 7) + ((lane >> 4) & 1) * 8, bK = ((lane >> 3) & 1) * 8;
    uint32_t wb_h = smb + ((warp_n * 16 + bRow) * LDW + bK) * 2;
    uint32_t wb_l = wb_h + GRUW_B;
    uint32_t hb_h = smb + 2 * GRUW_B + ((warp_m * 16 + aRow) * LDW + aK) * 2;
    uint32_t hb_l = hb_h + GRUH_B;

    for (int t = 0; t < NS; t++) {
        // stage h tile (32 rows x 512, hi+lo)
        for (int idx = tid; idx < 32 * 64; idx += 192) {
            int r = idx >> 6, c = idx & 63;
            *(uint4*)(sm + 2 * GRUW_B + r * (LDW * 2) + c * 16) =
                *(const uint4*)(hsh + (size_t)(mb * 32 + r) * DD + c * 8);
            *(uint4*)(sm + 2 * GRUW_B + GRUH_B + r * (LDW * 2) + c * 16) =
                *(const uint4*)(hsl + (size_t)(mb * 32 + r) * DD + c * 8);
        }
        __syncthreads();

        float acc0[4] = {0, 0, 0, 0}, acc1[4] = {0, 0, 0, 0};
        #pragma unroll 4
        for (int kc = 0; kc < 32; kc++) {
            uint32_t ah[4], al[4], bh[4], bl[4];
            ldsm_x4(ah, hb_h + kc * 32);
            ldsm_x4(al, hb_l + kc * 32);
            ldsm_x4(bh, wb_h + kc * 32);
            ldsm_x4(bl, wb_l + kc * 32);
            mma16816(acc0, ah, &bh[0]);
            mma16816(acc0, ah, &bl[0]);
            mma16816(acc0, al, &bh[0]);
            mma16816(acc1, ah, &bh[2]);
            mma16816(acc1, ah, &bl[2]);
            mma16816(acc1, al, &bh[2]);
        }

        // write G slice (fp32)
        {
            int gr0 = mb * 32 + warp_m * 16 + (lane >> 2);
            int gc  = nb * 48 + warp_n * 16 + (lane & 3) * 2;
            *(float2*)(G + (size_t)gr0 * D3 + gc)       = make_float2(acc0[0], acc0[1]);
            *(float2*)(G + (size_t)gr0 * D3 + gc + 8)   = make_float2(acc1[0], acc1[1]);
            *(float2*)(G + (size_t)(gr0 + 8) * D3 + gc)     = make_float2(acc0[2], acc0[3]);
            *(float2*)(G + (size_t)(gr0 + 8) * D3 + gc + 8) = make_float2(acc1[2], acc1[3]);
        }
        bar4(mb);

        // distributed pointwise: block nb handles j-slice [nb*16, nb*16+16) for its 32 m rows
        for (int idx = tid; idx < 512; idx += 192) {
            int m_loc = idx >> 4, j_loc = idx & 15;
            int b = mb * 32 + m_loc;
            int j = nb * 16 + j_loc;
            float gr = G[(size_t)b * D3 + j];
            float gz = G[(size_t)b * D3 + DD + j];
            float gn = G[(size_t)b * D3 + 2 * DD + j];
            size_t xb = ((size_t)b * NS + t) * D3 + j;
            float xr = xp[xb], xz = xp[xb + DD], xn = xp[xb + 2 * DD];
            float r = sigmoid_fast(xr + gr + bhh[j]);
            float z = sigmoid_fast(xz + gz + bhh[DD + j]);
            float n = tanh_fast(xn + r * (gn + bhh[2 * DD + j]));
            float hp = hstate[(size_t)b * DD + j];
            float h2 = (1.0f - z) * n + z * hp;
            hstate[(size_t)b * DD + j] = h2;
            __nv_bfloat16 hb16 = __float2bfloat16_rn(h2);
            __nv_bfloat16 lb16 = __float2bfloat16_rn(h2 - __bfloat162float(hb16));
            hsh[(size_t)b * DD + j] = hb16;
            hsl[(size_t)b * DD + j] = lb16;
            size_t yi = ((size_t)b * NS + t) * DD + j;
            yh[yi] = hb16;
            yl[yi] = lb16;
            if (nb == 0 && j_loc == 0) maskp[(size_t)b * NS + t] = (h2 != 0.0f) ? 1.0f : 0.0f;
        }
        bar4(mb);
    }
}

extern "C" void kernel_launch(void* const* d_in, const int* in_sizes, int n_in,
                              void* d_out, int out_size) {
    const int*   seqs  = (const int*)d_in[0];
    const float* enc   = (const float*)d_in[2];
    const float* h0    = (const float*)d_in[3];
    const float* emb   = (const float*)d_in[4];
    const float* w_ih  = (const float*)d_in[5];
    const float* w_hh  = (const float*)d_in[6];
    const float* b_ih  = (const float*)d_in[7];
    const float* b_hh  = (const float*)d_in[8];
    const float* attnw = (const float*)d_in[9];
    const float* attnb = (const float*)d_in[10];
    const float* outw  = (const float*)d_in[11];
    const float* outb  = (const float*)d_in[12];
    float* out = (float*)d_out;

    float *xp, *G, *hstate, *mask;
    __nv_bfloat16 *hsh, *hsl, *Ah, *Al, *Ph, *Pl, *Ch, *Cl, *Dh, *Dl;
    __nv_bfloat16 *ench, *encl, *encTh, *encTl, *wihh, *wihl, *whhh, *whhl, *awh, *awl, *owh, *owl;
    cudaGetSymbolAddress((void**)&xp,     g_xp);
    cudaGetSymbolAddress((void**)&G,      g_G);
    cudaGetSymbolAddress((void**)&hstate, g_h);
    cudaGetSymbolAddress((void**)&mask,   g_mask);
    cudaGetSymbolAddress((void**)&hsh, g_hsh);     cudaGetSymbolAddress((void**)&hsl, g_hsl);
    cudaGetSymbolAddress((void**)&Ah, g_Ah);   cudaGetSymbolAddress((void**)&Al, g_Al);
    cudaGetSymbolAddress((void**)&Ph, g_Ph);   cudaGetSymbolAddress((void**)&Pl, g_Pl);
    cudaGetSymbolAddress((void**)&Ch, g_Ch);   cudaGetSymbolAddress((void**)&Cl, g_Cl);
    cudaGetSymbolAddress((void**)&Dh, g_Dh);   cudaGetSymbolAddress((void**)&Dl, g_Dl);
    cudaGetSymbolAddress((void**)&ench, g_ench);   cudaGetSymbolAddress((void**)&encl, g_encl);
    cudaGetSymbolAddress((void**)&encTh, g_encTh); cudaGetSymbolAddress((void**)&encTl, g_encTl);
    cudaGetSymbolAddress((void**)&wihh, g_wihh);   cudaGetSymbolAddress((void**)&wihl, g_wihl);
    cudaGetSymbolAddress((void**)&whhh, g_whhh);   cudaGetSymbolAddress((void**)&whhl, g_whhl);
    cudaGetSymbolAddress((void**)&awh, g_awh);     cudaGetSymbolAddress((void**)&awl, g_awl);
    cudaGetSymbolAddress((void**)&owh, g_owh);     cudaGetSymbolAddress((void**)&owl, g_owl);

    static int attr_set = 0;
    if (!attr_set) {
        cudaFuncSetAttribute(gru_mma, cudaFuncAttributeMaxDynamicSharedMemorySize, GRU2_SMEM);
        cudaFuncSetAttribute(gemm_mma, cudaFuncAttributeMaxDynamicSharedMemorySize, GM_SMEM);
        attr_set = 1;
    }

    const size_t OUT_H    = (size_t)MALL * NV;
    const size_t OUT_ATTN = OUT_H + (size_t)NL * NB * DD;
    float* attnP = out + OUT_ATTN;
    const float SC = 0.044194173824159216f;

    split4_kernel<<<(NL * D3 * DD / 4 + 255) / 256, 256>>>(w_ih, wihh, wihl, NL * D3 * DD / 4);
    split4_kernel<<<(NL * D3 * DD / 4 + 255) / 256, 256>>>(w_hh, whhh, whhl, NL * D3 * DD / 4);
    split4_kernel<<<(DD * 2 * DD / 4 + 255) / 256, 256>>>(attnw, awh, awl, DD * 2 * DD / 4);
    splitpad_kernel<<<(128 * DD + 255) / 256, 256>>>(outw, owh, owl);
    split4_kernel<<<(NB * NSE * DD / 4 + 255) / 256, 256>>>(enc, ench, encl, NB * NSE * DD / 4);
    transpose_split_kernel<<<dim3(16, 16, 128), dim3(32, 8)>>>(enc, encTh, encTl);

    embed_split_kernel<<<(MALL * (DD / 4)) / 256, 256>>>(seqs, emb, Ah, Al);

    for (int l = 0; l < NL; l++) {
        // xp = x @ w_ih[l]^T + b_ih[l]   (plain layout, f32)
        gemm_mma<<<dim3(12, 512, 1), 256, GM_SMEM>>>(
            Ah, Al, nullptr, nullptr, DD, DD, DD,
            wihh + (size_t)l * D3 * DD, wihl + (size_t)l * D3 * DD, D3,
            xp, nullptr, nullptr, D3, 0, 0, 0, 1.0f, b_ih + (size_t)l * D3, nullptr, 0);
        h_init_kernel<<<(NB * DD / 4 + 255) / 256, 256>>>(
            h0 + (size_t)l * NB * DD, hstate, hsh, hsl);
        gru_mma<<<128, 192, GRU2_SMEM>>>(
            whhh + (size_t)l * D3 * DD, whhl + (size_t)l * D3 * DD,
            b_hh + (size_t)l * D3, xp, G, hstate, hsh, hsl, Ah, Al, mask);
        copy4_kernel<<<64, 256>>>(out + OUT_H + (size_t)l * NB * DD, hstate, NB * DD / 4);
    }

    // scores -> attnP (f32, output region)
    gemm_mma<<<dim3(4, 4, 128), 256, GM_SMEM>>>(
        Ah, Al, nullptr, nullptr, DD, DD, DD,
        ench, encl, NSE,
        attnP, nullptr, nullptr, NSE, (size_t)NS * DD, (size_t)NSE * DD, (size_t)NS * NSE,
        SC, nullptr, nullptr, 0);
    softmax_kernel<<<MALL, 256>>>(attnP, Ph, Pl);

    // context (bf16 split out)
    gemm_mma<<<dim3(4, 4, 128), 256, GM_SMEM>>>(
        Ph, Pl, nullptr, nullptr, NSE, NSE, NSE,
        encTh, encTl, DD,
        nullptr, Ch, Cl, DD, (size_t)NS * NSE, (size_t)DD * NSE, (size_t)NS * DD,
        1.0f, nullptr, nullptr, 4);

    // attn_masked = tanh([dec|ctx] @ attn_w^T + attn_b)*mask (bf16 split out)
    gemm_mma<<<dim3(4, 512, 1), 256, GM_SMEM>>>(
        Ah, Al, Ch, Cl, DD, DD, 2 * DD,
        awh, awl, DD,
        nullptr, Dh, Dl, DD, 0, 0, 0, 1.0f, attnb, mask, 5);

    // logits
    gemm_mma<<<dim3(1, 512, 1), 256, GM_SMEM>>>(
        Dh, Dl, nullptr, nullptr, DD, DD, DD,
        owh, owl, NV,
        out, nullptr, nullptr, NV, 0, 0, 0, 1.0f, outb, mask, 2);
}